// round 6
// baseline (speedup 1.0000x reference)
#include <cuda_runtime.h>
#include <mma.h>
#include <math.h>

using namespace nvcuda;

#define B_  4
#define T_  2048
#define D_  1024
#define H_  16
#define HD_ 64
#define MTOT (B_*T_)   // 8192

// Scratch (device globals: allocation-free rule)
__device__ float g_Q[MTOT*D_];
__device__ float g_K[MTOT*D_];
__device__ float g_V[MTOT*D_];
__device__ float g_A[MTOT*D_];

// ---- tf32x3 split helper: v = hi + lo (hi,lo both representable in tf32) ----
template <typename FragT>
__device__ __forceinline__ void split_frag(const FragT& f, FragT& hi, FragT& lo) {
    #pragma unroll
    for (int e = 0; e < f.num_elements; e++) {
        float v = f.x[e];
        float h = wmma::__float_to_tf32(v);
        hi.x[e] = h;
        lo.x[e] = wmma::__float_to_tf32(v - h);
    }
}

// ---------------------------------------------------------------------------
// GEMM: C[M,N] = A[M,K] @ W[N,K]^T + bias,  tf32x3 wmma, BM=128 BN=128 BK=32
// ---------------------------------------------------------------------------
#define BM 128
#define BN 128
#define BKK 32

__device__ __forceinline__ void gemm_bias_body(
    const float* __restrict__ A, const float* __restrict__ W,
    const float* __restrict__ bias, float* __restrict__ C,
    int M, int N, int K)
{
    __shared__ float Asm[BM][BKK+4];     // 128 x 36
    __shared__ float Bsm[BKK][BN+4];     // 32 x 132, Bsm[k][n] = W[n0+n][k0+k]
    __shared__ float stage[8][16][20];   // per-warp epilogue staging

    const int tid  = threadIdx.x;
    const int w    = tid >> 5;
    const int lane = tid & 31;
    const int warp_m = w >> 1;           // 0..3
    const int warp_n = w & 1;            // 0..1
    const int m0 = blockIdx.x * BM;
    const int n0 = blockIdx.y * BN;

    wmma::fragment<wmma::accumulator,16,16,8,float> c[2][4];
    #pragma unroll
    for (int i=0;i<2;i++)
        #pragma unroll
        for (int j=0;j<4;j++) wmma::fill_fragment(c[i][j], 0.f);

    for (int k0 = 0; k0 < K; k0 += BKK) {
        #pragma unroll
        for (int idx = tid; idx < 1024; idx += 256) {
            int r = idx >> 3, cg = idx & 7;
            float4 v = *reinterpret_cast<const float4*>(&A[(size_t)(m0+r)*K + k0 + cg*4]);
            *reinterpret_cast<float4*>(&Asm[r][cg*4]) = v;
        }
        #pragma unroll
        for (int idx = tid; idx < 1024; idx += 256) {
            int n = idx >> 3, cg = idx & 7;
            float4 v = *reinterpret_cast<const float4*>(&W[(size_t)(n0+n)*K + k0 + cg*4]);
            Bsm[cg*4+0][n] = v.x; Bsm[cg*4+1][n] = v.y;
            Bsm[cg*4+2][n] = v.z; Bsm[cg*4+3][n] = v.w;
        }
        __syncthreads();

        #pragma unroll
        for (int kk = 0; kk < BKK; kk += 8) {
            wmma::fragment<wmma::matrix_a,16,16,8,wmma::precision::tf32,wmma::row_major> araw, ahi[2], alo[2];
            wmma::fragment<wmma::matrix_b,16,16,8,wmma::precision::tf32,wmma::row_major> braw, bhi[4], blo[4];
            #pragma unroll
            for (int i=0;i<2;i++) {
                wmma::load_matrix_sync(araw, &Asm[warp_m*32 + i*16][kk], BKK+4);
                split_frag(araw, ahi[i], alo[i]);
            }
            #pragma unroll
            for (int j=0;j<4;j++) {
                wmma::load_matrix_sync(braw, &Bsm[kk][warp_n*64 + j*16], BN+4);
                split_frag(braw, bhi[j], blo[j]);
            }
            #pragma unroll
            for (int i=0;i<2;i++)
                #pragma unroll
                for (int j=0;j<4;j++) {
                    wmma::mma_sync(c[i][j], ahi[i], blo[j], c[i][j]);
                    wmma::mma_sync(c[i][j], alo[i], bhi[j], c[i][j]);
                    wmma::mma_sync(c[i][j], ahi[i], bhi[j], c[i][j]);
                }
        }
        __syncthreads();
    }

    // epilogue with bias through per-warp smem staging
    #pragma unroll
    for (int i=0;i<2;i++)
        #pragma unroll
        for (int j=0;j<4;j++) {
            wmma::store_matrix_sync(&stage[w][0][0], c[i][j], 20, wmma::mem_row_major);
            __syncwarp();
            int gmb = m0 + warp_m*32 + i*16;
            int gnb = n0 + warp_n*64 + j*16;
            #pragma unroll
            for (int e = lane; e < 256; e += 32) {
                int r = e >> 4, cc = e & 15;
                C[(size_t)(gmb+r)*N + gnb+cc] = stage[w][r][cc] + bias[gnb+cc];
            }
            __syncwarp();
        }
}

__global__ __launch_bounds__(256) void gemm_bias_kernel(
    const float* __restrict__ A, const float* __restrict__ W,
    const float* __restrict__ bias, float* __restrict__ C,
    int M, int N, int K)
{
    gemm_bias_body(A, W, bias, C, M, N, K);
}

// Fused QKV: grid.z in {0,1,2} selects {wq->Q, wk->K, wv->V}
__global__ __launch_bounds__(256) void gemm_qkv_kernel(
    const float* __restrict__ x,
    const float* __restrict__ wq, const float* __restrict__ bq, float* __restrict__ Qo,
    const float* __restrict__ wk, const float* __restrict__ bk, float* __restrict__ Ko,
    const float* __restrict__ wv, const float* __restrict__ bv, float* __restrict__ Vo)
{
    const float* W; const float* bias; float* C;
    if (blockIdx.z == 0)      { W = wq; bias = bq; C = Qo; }
    else if (blockIdx.z == 1) { W = wk; bias = bk; C = Ko; }
    else                      { W = wv; bias = bv; C = Vo; }
    gemm_bias_body(x, W, bias, C, MTOT, D_, D_);
}

// ---------------------------------------------------------------------------
// Flash attention (causal): per-(b,h) Q tile of 128 rows, key tiles of 64
// Q/K/V in canonical [B*T, D] layout; head h is column slice [h*64, h*64+64)
// ---------------------------------------------------------------------------
#define BR 128
#define BC 64
#define QPITCH 68

__global__ __launch_bounds__(256) void flash_kernel(
    const float* __restrict__ Q, const float* __restrict__ K,
    const float* __restrict__ V, float* __restrict__ Aout)
{
    extern __shared__ float sm[];
    float* Qsm  = sm;                      // [128][68] (pre-scaled)
    float* Ksm  = Qsm  + 128*QPITCH;       // [64][68]
    float* Vsm  = Ksm  +  64*QPITCH;       // [64][68]
    float* Ssm  = Vsm  +  64*QPITCH;       // [128][68] (S, then P, then PV)
    float* Osm  = Ssm  + 128*QPITCH;       // [128][64]
    float* mrow = Osm  + 128*64;           // [128]
    float* lrow = mrow + 128;              // [128]
    float* arow = lrow + 128;              // [128]

    const int tid  = threadIdx.x;
    const int w    = tid >> 5;
    const int bh   = blockIdx.y;
    const int b    = bh / H_;
    const int h    = bh % H_;
    const int qt0  = blockIdx.x * BR;
    const float scale = 0.125f;            // 1/sqrt(64)

    const size_t qbase = (size_t)(b*T_ + qt0) * D_ + h*HD_;

    // load Q tile (scaled): 128x64 = 2048 float4
    #pragma unroll
    for (int idx = tid; idx < 2048; idx += 256) {
        int r = idx >> 4, cg = idx & 15;
        float4 v = *reinterpret_cast<const float4*>(&Q[qbase + (size_t)r*D_ + cg*4]);
        v.x *= scale; v.y *= scale; v.z *= scale; v.w *= scale;
        *reinterpret_cast<float4*>(&Qsm[r*QPITCH + cg*4]) = v;
    }
    if (tid < 128) { mrow[tid] = -INFINITY; lrow[tid] = 0.f; }
    for (int idx = tid; idx < 128*64; idx += 256) Osm[idx] = 0.f;
    __syncthreads();

    const int njt = qt0/BC + 2;  // causal: only key tiles up to the diagonal
    for (int j = 0; j < njt; j++) {
        const int s0 = j * BC;
        const size_t kvbase = (size_t)(b*T_ + s0) * D_ + h*HD_;
        // load K and V tiles (64x64 each)
        #pragma unroll
        for (int idx = tid; idx < 2048; idx += 256) {
            int which = idx >> 10;
            int e = idx & 1023;
            int r = e >> 4, cg = e & 15;
            const float* src = which ? V : K;
            float4 v = *reinterpret_cast<const float4*>(&src[kvbase + (size_t)r*D_ + cg*4]);
            float* dst = which ? Vsm : Ksm;
            *reinterpret_cast<float4*>(&dst[r*QPITCH + cg*4]) = v;
        }
        __syncthreads();

        // S = Qs @ K^T : [128x64]; warps 4(m) x 2(n), each 32x32  (tf32x3)
        {
            const int wm = w >> 1, wn = w & 1;
            wmma::fragment<wmma::accumulator,16,16,8,float> cfr[2][2];
            #pragma unroll
            for (int i=0;i<2;i++)
                #pragma unroll
                for (int jj=0;jj<2;jj++) wmma::fill_fragment(cfr[i][jj], 0.f);
            #pragma unroll
            for (int kk = 0; kk < HD_; kk += 8) {
                wmma::fragment<wmma::matrix_a,16,16,8,wmma::precision::tf32,wmma::row_major> araw, ahi[2], alo[2];
                wmma::fragment<wmma::matrix_b,16,16,8,wmma::precision::tf32,wmma::col_major> braw, bhi[2], blo[2];
                #pragma unroll
                for (int i=0;i<2;i++) {
                    wmma::load_matrix_sync(araw, &Qsm[(wm*32+i*16)*QPITCH + kk], QPITCH);
                    split_frag(araw, ahi[i], alo[i]);
                }
                #pragma unroll
                for (int jj=0;jj<2;jj++) {
                    wmma::load_matrix_sync(braw, &Ksm[(wn*32+jj*16)*QPITCH + kk], QPITCH);
                    split_frag(braw, bhi[jj], blo[jj]);
                }
                #pragma unroll
                for (int i=0;i<2;i++)
                    #pragma unroll
                    for (int jj=0;jj<2;jj++) {
                        wmma::mma_sync(cfr[i][jj], ahi[i], blo[jj], cfr[i][jj]);
                        wmma::mma_sync(cfr[i][jj], alo[i], bhi[jj], cfr[i][jj]);
                        wmma::mma_sync(cfr[i][jj], ahi[i], bhi[jj], cfr[i][jj]);
                    }
            }
            #pragma unroll
            for (int i=0;i<2;i++)
                #pragma unroll
                for (int jj=0;jj<2;jj++)
                    wmma::store_matrix_sync(&Ssm[(wm*32+i*16)*QPITCH + wn*32+jj*16],
                                            cfr[i][jj], QPITCH, wmma::mem_row_major);
        }
        __syncthreads();

        // online softmax: one thread per row
        if (tid < 128) {
            const int r = tid;
            const int qrow = qt0 + r;
            const float mold = mrow[r];
            int clim = qrow - s0;            // valid cols c <= clim (causal)
            if (clim > BC-1) clim = BC-1;
            float mt = -INFINITY;
            for (int c = 0; c <= clim; c++) mt = fmaxf(mt, Ssm[r*QPITCH+c]);
            const float mnew = fmaxf(mold, mt);
            const float alpha = __expf(mold - mnew);   // -inf first time -> 0
            float lsum = 0.f;
            for (int c = 0; c <= clim; c++) {
                float p = __expf(Ssm[r*QPITCH+c] - mnew);
                Ssm[r*QPITCH+c] = p;
                lsum += p;
            }
            // BUGFIX: clamp start to 0 — clim can be negative (fully-masked row
            // in this tile); starting at clim+1 < 0 wrote zeros into row r-1's
            // valid P columns (the 3.3e-3 corruption).
            int zstart = clim + 1; if (zstart < 0) zstart = 0;
            for (int c = zstart; c < BC; c++) Ssm[r*QPITCH+c] = 0.f;
            mrow[r] = mnew;
            lrow[r] = lrow[r]*alpha + lsum;
            arow[r] = alpha;
        }
        __syncthreads();

        // PV = P @ V : each warp 16 rows x 64 cols; tf32x3; overwrites P in Ssm
        {
            wmma::fragment<wmma::accumulator,16,16,8,float> pv[4];
            #pragma unroll
            for (int jj=0;jj<4;jj++) wmma::fill_fragment(pv[jj], 0.f);
            #pragma unroll
            for (int kk = 0; kk < BC; kk += 8) {
                wmma::fragment<wmma::matrix_a,16,16,8,wmma::precision::tf32,wmma::row_major> araw, ahi, alo;
                wmma::load_matrix_sync(araw, &Ssm[(w*16)*QPITCH + kk], QPITCH);
                split_frag(araw, ahi, alo);
                wmma::fragment<wmma::matrix_b,16,16,8,wmma::precision::tf32,wmma::row_major> braw, bhi[4], blo[4];
                #pragma unroll
                for (int jj=0;jj<4;jj++) {
                    wmma::load_matrix_sync(braw, &Vsm[kk*QPITCH + jj*16], QPITCH);
                    split_frag(braw, bhi[jj], blo[jj]);
                }
                #pragma unroll
                for (int jj=0;jj<4;jj++) {
                    wmma::mma_sync(pv[jj], ahi, blo[jj], pv[jj]);
                    wmma::mma_sync(pv[jj], alo, bhi[jj], pv[jj]);
                    wmma::mma_sync(pv[jj], ahi, bhi[jj], pv[jj]);
                }
            }
            #pragma unroll
            for (int jj=0;jj<4;jj++)
                wmma::store_matrix_sync(&Ssm[(w*16)*QPITCH + jj*16], pv[jj], QPITCH,
                                        wmma::mem_row_major);
        }
        __syncthreads();

        // O = O*alpha + PV
        {
            const int r = tid >> 1, half = tid & 1;
            const float alpha = arow[r];
            #pragma unroll
            for (int c = half*32; c < half*32+32; c++)
                Osm[r*64+c] = Osm[r*64+c]*alpha + Ssm[r*QPITCH+c];
        }
        __syncthreads();
    }

    // epilogue: normalize and write attention output (canonical layout)
    {
        const size_t obase = (size_t)(b*T_ + qt0) * D_ + h*HD_;
        for (int idx = tid; idx < 128*64; idx += 256) {
            int r = idx >> 6, c = idx & 63;
            Aout[obase + (size_t)r*D_ + c] = Osm[r*64+c] / lrow[r];
        }
    }
}

// ---------------------------------------------------------------------------
// Launch
// ---------------------------------------------------------------------------
static const int FLASH_SMEM =
    (128*QPITCH + 64*QPITCH + 64*QPITCH + 128*QPITCH + 128*64 + 3*128) * (int)sizeof(float);

extern "C" void kernel_launch(void* const* d_in, const int* in_sizes, int n_in,
                              void* d_out, int out_size)
{
    const float* x  = (const float*)d_in[0];
    const float* wq = (const float*)d_in[1];
    const float* bq = (const float*)d_in[2];
    const float* wk = (const float*)d_in[3];
    const float* bk = (const float*)d_in[4];
    const float* wv = (const float*)d_in[5];
    const float* bv = (const float*)d_in[6];
    const float* wo = (const float*)d_in[7];
    const float* bo = (const float*)d_in[8];
    // d_in[9] is the causal mask; causality is applied analytically in flash_kernel.
    float* out = (float*)d_out;

    float *qb, *kb, *vb, *ab;
    cudaGetSymbolAddress((void**)&qb, g_Q);
    cudaGetSymbolAddress((void**)&kb, g_K);
    cudaGetSymbolAddress((void**)&vb, g_V);
    cudaGetSymbolAddress((void**)&ab, g_A);

    cudaFuncSetAttribute(flash_kernel, cudaFuncAttributeMaxDynamicSharedMemorySize, FLASH_SMEM);

    dim3 qkv_grid(MTOT/BM, D_/BN, 3);   // (64, 8, 3)
    gemm_qkv_kernel<<<qkv_grid, 256>>>(x, wq, bq, qb, wk, bk, kb, wv, bv, vb);

    dim3 flash_grid(T_/BR, B_*H_);      // (16, 64)
    flash_kernel<<<flash_grid, 256, FLASH_SMEM>>>(qb, kb, vb, ab);

    dim3 gemm_grid(MTOT/BM, D_/BN);     // (64, 8)
    gemm_bias_kernel<<<gemm_grid, 256>>>(ab, wo, bo, out, MTOT, D_, D_);
}

// round 8
// speedup vs baseline: 1.3310x; 1.3310x over previous
#include <cuda_runtime.h>
#include <cstdint>
#include <mma.h>
#include <math.h>

using namespace nvcuda;

#define B_  4
#define T_  2048
#define D_  1024
#define H_  16
#define HD_ 64
#define MTOT (B_*T_)   // 8192

// Scratch (device globals: allocation-free rule)
__device__ float g_Q[MTOT*D_];
__device__ float g_K[MTOT*D_];
__device__ float g_V[MTOT*D_];
__device__ float g_A[MTOT*D_];

// ---- tf32x3 split helper: v = hi + lo (projections only) ----
template <typename FragT>
__device__ __forceinline__ void split_frag(const FragT& f, FragT& hi, FragT& lo) {
    #pragma unroll
    for (int e = 0; e < f.num_elements; e++) {
        float v = f.x[e];
        float h = wmma::__float_to_tf32(v);
        hi.x[e] = h;
        lo.x[e] = wmma::__float_to_tf32(v - h);
    }
}

template <typename FragT>
__device__ __forceinline__ void cvt_frag(FragT& f) {
    #pragma unroll
    for (int e = 0; e < f.num_elements; e++) f.x[e] = wmma::__float_to_tf32(f.x[e]);
}

__device__ __forceinline__ void cp16(uint32_t saddr, const void* g) {
    asm volatile("cp.async.cg.shared.global [%0], [%1], 16;" :: "r"(saddr), "l"(g));
}

// ---------------------------------------------------------------------------
// GEMM: C[M,N] = A[M,K] @ W[N,K]^T + bias, tf32x3, 2-stage cp.async pipeline
// BM=128 BN=128 BK=32.  Both A and W tiles are [128 rows][32 k] + 4 pad.
// ---------------------------------------------------------------------------
#define BM 128
#define BN 128
#define BKK 32
#define TP 36                      // tile row pitch (floats)
#define AST (128*TP)               // floats per tile stage
static const int GEMM_DSMEM = (4*AST) * (int)sizeof(float);   // 2 stages x (A+W) = 73728 B

__device__ __forceinline__ void gemm_bias_body(
    const float* __restrict__ A, const float* __restrict__ W,
    const float* __restrict__ bias, float* __restrict__ C,
    int M, int N, int K)
{
    extern __shared__ float dynsm[];
    float* Asm = dynsm;            // [2][128][36]
    float* Wsm = dynsm + 2*AST;    // [2][128][36]
    const uint32_t smbase = (uint32_t)__cvta_generic_to_shared(dynsm);

    const int tid  = threadIdx.x;
    const int w    = tid >> 5;
    const int lane = tid & 31;
    const int warp_m = w >> 1;           // 0..3
    const int warp_n = w & 1;            // 0..1
    const int m0 = blockIdx.x * BM;
    const int n0 = blockIdx.y * BN;

    wmma::fragment<wmma::accumulator,16,16,8,float> c[2][4];
    #pragma unroll
    for (int i=0;i<2;i++)
        #pragma unroll
        for (int j=0;j<4;j++) wmma::fill_fragment(c[i][j], 0.f);

    const int NIT = K / BKK;   // 32

    // async tile loader: A rows and W rows, 16B chunks (8 per row)
    auto issue_tiles = [&](int k0, int s) {
        const uint32_t abase = smbase + (uint32_t)(s*AST)*4u;
        const uint32_t wbase = smbase + (uint32_t)(2*AST + s*AST)*4u;
        #pragma unroll
        for (int idx = tid; idx < 1024; idx += 256) {
            int r = idx >> 3, cg = idx & 7;
            cp16(abase + (uint32_t)(r*TP + cg*4)*4u, &A[(size_t)(m0+r)*K + k0 + cg*4]);
        }
        #pragma unroll
        for (int idx = tid; idx < 1024; idx += 256) {
            int n = idx >> 3, cg = idx & 7;
            cp16(wbase + (uint32_t)(n*TP + cg*4)*4u, &W[(size_t)(n0+n)*K + k0 + cg*4]);
        }
        asm volatile("cp.async.commit_group;");
    };

    issue_tiles(0, 0);

    for (int it = 0; it < NIT; it++) {
        const int cur = it & 1;
        if (it + 1 < NIT) {
            issue_tiles((it+1)*BKK, (it+1) & 1);
            asm volatile("cp.async.wait_group 1;");
        } else {
            asm volatile("cp.async.wait_group 0;");
        }
        __syncthreads();

        const float* At = Asm + cur*AST;
        const float* Wt = Wsm + cur*AST;
        #pragma unroll
        for (int kk = 0; kk < BKK; kk += 8) {
            wmma::fragment<wmma::matrix_a,16,16,8,wmma::precision::tf32,wmma::row_major> araw, ahi[2], alo[2];
            wmma::fragment<wmma::matrix_b,16,16,8,wmma::precision::tf32,wmma::col_major> braw, bhi[4], blo[4];
            #pragma unroll
            for (int i=0;i<2;i++) {
                wmma::load_matrix_sync(araw, &At[(warp_m*32 + i*16)*TP + kk], TP);
                split_frag(araw, ahi[i], alo[i]);
            }
            #pragma unroll
            for (int j=0;j<4;j++) {
                wmma::load_matrix_sync(braw, &Wt[(warp_n*64 + j*16)*TP + kk], TP);
                split_frag(braw, bhi[j], blo[j]);
            }
            #pragma unroll
            for (int i=0;i<2;i++)
                #pragma unroll
                for (int j=0;j<4;j++) {
                    wmma::mma_sync(c[i][j], ahi[i], blo[j], c[i][j]);
                    wmma::mma_sync(c[i][j], alo[i], bhi[j], c[i][j]);
                    wmma::mma_sync(c[i][j], ahi[i], bhi[j], c[i][j]);
                }
        }
        __syncthreads();
    }

    // epilogue with bias; reuse pipeline smem as per-warp staging [8][16][20]
    float* stage = dynsm + w*(16*20);
    #pragma unroll
    for (int i=0;i<2;i++)
        #pragma unroll
        for (int j=0;j<4;j++) {
            wmma::store_matrix_sync(stage, c[i][j], 20, wmma::mem_row_major);
            __syncwarp();
            int gmb = m0 + warp_m*32 + i*16;
            int gnb = n0 + warp_n*64 + j*16;
            #pragma unroll
            for (int e = lane; e < 256; e += 32) {
                int r = e >> 4, cc = e & 15;
                C[(size_t)(gmb+r)*N + gnb+cc] = stage[r*20+cc] + bias[gnb+cc];
            }
            __syncwarp();
        }
}

__global__ __launch_bounds__(256) void gemm_bias_kernel(
    const float* __restrict__ A, const float* __restrict__ W,
    const float* __restrict__ bias, float* __restrict__ C,
    int M, int N, int K)
{
    gemm_bias_body(A, W, bias, C, M, N, K);
}

// Fused QKV: grid.z in {0,1,2} selects {wq->Q, wk->K, wv->V}
__global__ __launch_bounds__(256) void gemm_qkv_kernel(
    const float* __restrict__ x,
    const float* __restrict__ wq, const float* __restrict__ bq, float* __restrict__ Qo,
    const float* __restrict__ wk, const float* __restrict__ bk, float* __restrict__ Ko,
    const float* __restrict__ wv, const float* __restrict__ bv, float* __restrict__ Vo)
{
    const float* W; const float* bias; float* C;
    if (blockIdx.z == 0)      { W = wq; bias = bq; C = Qo; }
    else if (blockIdx.z == 1) { W = wk; bias = bk; C = Ko; }
    else                      { W = wv; bias = bv; C = Vo; }
    gemm_bias_body(x, W, bias, C, MTOT, D_, D_);
}

// ---------------------------------------------------------------------------
// Flash attention (causal), single-pass TF32 MMAs, 2 threads/row softmax
// ---------------------------------------------------------------------------
#define BR 128
#define BC 64
#define QPITCH 68

__global__ __launch_bounds__(256) void flash_kernel(
    const float* __restrict__ Q, const float* __restrict__ K,
    const float* __restrict__ V, float* __restrict__ Aout)
{
    extern __shared__ float sm[];
    float* Qsm  = sm;                      // [128][68] (pre-scaled)
    float* Ksm  = Qsm  + 128*QPITCH;       // [64][68]
    float* Vsm  = Ksm  +  64*QPITCH;       // [64][68]
    float* Ssm  = Vsm  +  64*QPITCH;       // [128][68]
    float* Osm  = Ssm  + 128*QPITCH;       // [128][64]
    float* mrow = Osm  + 128*64;           // [128]
    float* lrow = mrow + 128;              // [128]
    float* arow = lrow + 128;              // [128]

    const int tid  = threadIdx.x;
    const int w    = tid >> 5;
    const int bh   = blockIdx.y;
    const int b    = bh / H_;
    const int h    = bh % H_;
    const int qt0  = blockIdx.x * BR;
    const float scale = 0.125f;            // 1/sqrt(64)

    const size_t qbase = (size_t)(b*T_ + qt0) * D_ + h*HD_;

    #pragma unroll
    for (int idx = tid; idx < 2048; idx += 256) {
        int r = idx >> 4, cg = idx & 15;
        float4 v = *reinterpret_cast<const float4*>(&Q[qbase + (size_t)r*D_ + cg*4]);
        v.x *= scale; v.y *= scale; v.z *= scale; v.w *= scale;
        *reinterpret_cast<float4*>(&Qsm[r*QPITCH + cg*4]) = v;
    }
    if (tid < 128) { mrow[tid] = -INFINITY; lrow[tid] = 0.f; }
    for (int idx = tid; idx < 128*64; idx += 256) Osm[idx] = 0.f;
    __syncthreads();

    const int njt = qt0/BC + 2;  // causal: only key tiles up to the diagonal
    for (int j = 0; j < njt; j++) {
        const int s0 = j * BC;
        const size_t kvbase = (size_t)(b*T_ + s0) * D_ + h*HD_;
        #pragma unroll
        for (int idx = tid; idx < 2048; idx += 256) {
            int which = idx >> 10;
            int e = idx & 1023;
            int r = e >> 4, cg = e & 15;
            const float* src = which ? V : K;
            float4 v = *reinterpret_cast<const float4*>(&src[kvbase + (size_t)r*D_ + cg*4]);
            float* dst = which ? Vsm : Ksm;
            *reinterpret_cast<float4*>(&dst[r*QPITCH + cg*4]) = v;
        }
        __syncthreads();

        // S = Qs @ K^T : [128x64]; warps 4(m) x 2(n); single-pass TF32
        {
            const int wm = w >> 1, wn = w & 1;
            wmma::fragment<wmma::accumulator,16,16,8,float> cfr[2][2];
            #pragma unroll
            for (int i=0;i<2;i++)
                #pragma unroll
                for (int jj=0;jj<2;jj++) wmma::fill_fragment(cfr[i][jj], 0.f);
            #pragma unroll
            for (int kk = 0; kk < HD_; kk += 8) {
                wmma::fragment<wmma::matrix_a,16,16,8,wmma::precision::tf32,wmma::row_major> af[2];
                wmma::fragment<wmma::matrix_b,16,16,8,wmma::precision::tf32,wmma::col_major> bf[2];
                #pragma unroll
                for (int i=0;i<2;i++) {
                    wmma::load_matrix_sync(af[i], &Qsm[(wm*32+i*16)*QPITCH + kk], QPITCH);
                    cvt_frag(af[i]);
                }
                #pragma unroll
                for (int jj=0;jj<2;jj++) {
                    wmma::load_matrix_sync(bf[jj], &Ksm[(wn*32+jj*16)*QPITCH + kk], QPITCH);
                    cvt_frag(bf[jj]);
                }
                #pragma unroll
                for (int i=0;i<2;i++)
                    #pragma unroll
                    for (int jj=0;jj<2;jj++)
                        wmma::mma_sync(cfr[i][jj], af[i], bf[jj], cfr[i][jj]);
            }
            #pragma unroll
            for (int i=0;i<2;i++)
                #pragma unroll
                for (int jj=0;jj<2;jj++)
                    wmma::store_matrix_sync(&Ssm[(wm*32+i*16)*QPITCH + wn*32+jj*16],
                                            cfr[i][jj], QPITCH, wmma::mem_row_major);
        }
        __syncthreads();

        // online softmax: 2 threads per row (halves combined via shfl_xor 1)
        {
            const int r = tid >> 1, half = tid & 1;
            const int qrow = qt0 + r;
            const float mold = mrow[r];
            int clim = qrow - s0;            // valid cols c <= clim (may be <0)
            if (clim > BC-1) clim = BC-1;
            const int c0 = half*32;
            float mt = -INFINITY;
            #pragma unroll
            for (int c = c0; c < c0+32; c++)
                if (c <= clim) mt = fmaxf(mt, Ssm[r*QPITCH+c]);
            mt = fmaxf(mt, __shfl_xor_sync(0xffffffffu, mt, 1));
            const float mnew = fmaxf(mold, mt);
            const float alpha = __expf(mold - mnew);   // mold=-inf first tile -> 0
            float lsum = 0.f;
            #pragma unroll
            for (int c = c0; c < c0+32; c++) {
                float p = (c <= clim) ? __expf(Ssm[r*QPITCH+c] - mnew) : 0.f;
                Ssm[r*QPITCH+c] = p;
                lsum += p;
            }
            lsum += __shfl_xor_sync(0xffffffffu, lsum, 1);
            if (half == 0) {
                mrow[r] = mnew;
                lrow[r] = lrow[r]*alpha + lsum;
                arow[r] = alpha;
            }
        }
        __syncthreads();

        // PV = P @ V : each warp 16 rows x 64 cols; single-pass TF32
        {
            wmma::fragment<wmma::accumulator,16,16,8,float> pv[4];
            #pragma unroll
            for (int jj=0;jj<4;jj++) wmma::fill_fragment(pv[jj], 0.f);
            #pragma unroll
            for (int kk = 0; kk < BC; kk += 8) {
                wmma::fragment<wmma::matrix_a,16,16,8,wmma::precision::tf32,wmma::row_major> af;
                wmma::load_matrix_sync(af, &Ssm[(w*16)*QPITCH + kk], QPITCH);
                cvt_frag(af);
                wmma::fragment<wmma::matrix_b,16,16,8,wmma::precision::tf32,wmma::row_major> bf[4];
                #pragma unroll
                for (int jj=0;jj<4;jj++) {
                    wmma::load_matrix_sync(bf[jj], &Vsm[kk*QPITCH + jj*16], QPITCH);
                    cvt_frag(bf[jj]);
                }
                #pragma unroll
                for (int jj=0;jj<4;jj++) wmma::mma_sync(pv[jj], af, bf[jj], pv[jj]);
            }
            #pragma unroll
            for (int jj=0;jj<4;jj++)
                wmma::store_matrix_sync(&Ssm[(w*16)*QPITCH + jj*16], pv[jj], QPITCH,
                                        wmma::mem_row_major);
        }
        __syncthreads();

        // O = O*alpha + PV
        {
            const int r = tid >> 1, half = tid & 1;
            const float alpha = arow[r];
            #pragma unroll
            for (int c = half*32; c < half*32+32; c++)
                Osm[r*64+c] = Osm[r*64+c]*alpha + Ssm[r*QPITCH+c];
        }
        __syncthreads();
    }

    // epilogue: normalize and write attention output (canonical layout)
    {
        const size_t obase = (size_t)(b*T_ + qt0) * D_ + h*HD_;
        for (int idx = tid; idx < 128*64; idx += 256) {
            int r = idx >> 6, c = idx & 63;
            Aout[obase + (size_t)r*D_ + c] = Osm[r*64+c] / lrow[r];
        }
    }
}

// ---------------------------------------------------------------------------
// Launch
// ---------------------------------------------------------------------------
static const int FLASH_SMEM =
    (128*QPITCH + 64*QPITCH + 64*QPITCH + 128*QPITCH + 128*64 + 3*128) * (int)sizeof(float);

extern "C" void kernel_launch(void* const* d_in, const int* in_sizes, int n_in,
                              void* d_out, int out_size)
{
    const float* x  = (const float*)d_in[0];
    const float* wq = (const float*)d_in[1];
    const float* bq = (const float*)d_in[2];
    const float* wk = (const float*)d_in[3];
    const float* bk = (const float*)d_in[4];
    const float* wv = (const float*)d_in[5];
    const float* bv = (const float*)d_in[6];
    const float* wo = (const float*)d_in[7];
    const float* bo = (const float*)d_in[8];
    // d_in[9] is the causal mask; causality is applied analytically in flash_kernel.
    float* out = (float*)d_out;

    float *qb, *kb, *vb, *ab;
    cudaGetSymbolAddress((void**)&qb, g_Q);
    cudaGetSymbolAddress((void**)&kb, g_K);
    cudaGetSymbolAddress((void**)&vb, g_V);
    cudaGetSymbolAddress((void**)&ab, g_A);

    cudaFuncSetAttribute(flash_kernel, cudaFuncAttributeMaxDynamicSharedMemorySize, FLASH_SMEM);
    cudaFuncSetAttribute(gemm_qkv_kernel, cudaFuncAttributeMaxDynamicSharedMemorySize, GEMM_DSMEM);
    cudaFuncSetAttribute(gemm_bias_kernel, cudaFuncAttributeMaxDynamicSharedMemorySize, GEMM_DSMEM);

    dim3 qkv_grid(MTOT/BM, D_/BN, 3);   // (64, 8, 3)
    gemm_qkv_kernel<<<qkv_grid, 256, GEMM_DSMEM>>>(x, wq, bq, qb, wk, bk, kb, wv, bv, vb);

    dim3 flash_grid(T_/BR, B_*H_);      // (16, 64)
    flash_kernel<<<flash_grid, 256, FLASH_SMEM>>>(qb, kb, vb, ab);

    dim3 gemm_grid(MTOT/BM, D_/BN);     // (64, 8)
    gemm_bias_kernel<<<gemm_grid, 256, GEMM_DSMEM>>>(ab, wo, bo, out, MTOT, D_, D_);
}

// round 9
// speedup vs baseline: 2.0331x; 1.5275x over previous
#include <cuda_runtime.h>
#include <cstdint>
#include <cuda_bf16.h>
#include <mma.h>
#include <math.h>

using namespace nvcuda;

#define B_  4
#define T_  2048
#define D_  1024
#define H_  16
#define HD_ 64
#define MTOT (B_*T_)   // 8192
#define DD  (D_*D_)    // 1048576

// Scratch (device globals: allocation-free rule)
__device__ float g_Q[MTOT*D_];
__device__ float g_K[MTOT*D_];
__device__ float g_V[MTOT*D_];
__device__ float g_A[MTOT*D_];
// bf16 hi/lo split operands
__device__ __nv_bfloat16 g_xhi[MTOT*D_];
__device__ __nv_bfloat16 g_xlo[MTOT*D_];
__device__ __nv_bfloat16 g_ahi[MTOT*D_];
__device__ __nv_bfloat16 g_alo[MTOT*D_];
__device__ __nv_bfloat16 g_whi[4*DD];   // wq, wk, wv, wo
__device__ __nv_bfloat16 g_wlo[4*DD];

// ---------------------------------------------------------------------------
// Split fp32 -> bf16 hi + bf16 lo
// ---------------------------------------------------------------------------
__global__ __launch_bounds__(256) void split_kernel(
    const float* __restrict__ src, __nv_bfloat16* __restrict__ hi,
    __nv_bfloat16* __restrict__ lo, int n)
{
    int i = blockIdx.x*blockDim.x + threadIdx.x;
    int stride = gridDim.x*blockDim.x;
    for (; i < n/4; i += stride) {
        float4 v = reinterpret_cast<const float4*>(src)[i];
        __nv_bfloat16 h0 = __float2bfloat16(v.x);
        __nv_bfloat16 h1 = __float2bfloat16(v.y);
        __nv_bfloat16 h2 = __float2bfloat16(v.z);
        __nv_bfloat16 h3 = __float2bfloat16(v.w);
        __nv_bfloat162 hA; hA.x = h0; hA.y = h1;
        __nv_bfloat162 hB; hB.x = h2; hB.y = h3;
        __nv_bfloat162 lA, lB;
        lA.x = __float2bfloat16(v.x - __bfloat162float(h0));
        lA.y = __float2bfloat16(v.y - __bfloat162float(h1));
        lB.x = __float2bfloat16(v.z - __bfloat162float(h2));
        lB.y = __float2bfloat16(v.w - __bfloat162float(h3));
        reinterpret_cast<__nv_bfloat162*>(hi)[i*2+0] = hA;
        reinterpret_cast<__nv_bfloat162*>(hi)[i*2+1] = hB;
        reinterpret_cast<__nv_bfloat162*>(lo)[i*2+0] = lA;
        reinterpret_cast<__nv_bfloat162*>(lo)[i*2+1] = lB;
    }
}

__device__ __forceinline__ void cp16(uint32_t saddr, const void* g) {
    asm volatile("cp.async.cg.shared.global [%0], [%1], 16;" :: "r"(saddr), "l"(g));
}

template <typename FragT>
__device__ __forceinline__ void cvt_frag(FragT& f) {
    #pragma unroll
    for (int e = 0; e < f.num_elements; e++) f.x[e] = wmma::__float_to_tf32(f.x[e]);
}

// ---------------------------------------------------------------------------
// GEMM: C[M,N] = A[M,K] @ W[N,K]^T + bias, bf16x3, 2-stage cp.async pipeline
// A/W pre-split into bf16 hi/lo. BM=128 BN=128 BK=32, k=16 per MMA.
// ---------------------------------------------------------------------------
#define BM 128
#define BN 128
#define BKK 32
#define TPB 40                       // bf16 tile row pitch (80 bytes)
#define TSTB (128*TPB)               // bf16 elems per tile
// stage = Ahi,Alo,Whi,Wlo tiles; 2 stages
static const int GEMM_DSMEM = (8*TSTB) * (int)sizeof(__nv_bfloat16);   // 81920 B

__device__ __forceinline__ void gemm_bias_body(
    const __nv_bfloat16* __restrict__ Ahi, const __nv_bfloat16* __restrict__ Alo,
    const __nv_bfloat16* __restrict__ Whi, const __nv_bfloat16* __restrict__ Wlo,
    const float* __restrict__ bias, float* __restrict__ C,
    int M, int N, int K)
{
    extern __shared__ __nv_bfloat16 dynsmb[];
    const uint32_t smbase = (uint32_t)__cvta_generic_to_shared(dynsmb);

    const int tid  = threadIdx.x;
    const int w    = tid >> 5;
    const int lane = tid & 31;
    const int warp_m = w >> 1;           // 0..3
    const int warp_n = w & 1;            // 0..1
    const int m0 = blockIdx.x * BM;
    const int n0 = blockIdx.y * BN;

    wmma::fragment<wmma::accumulator,16,16,16,float> c[2][4];
    #pragma unroll
    for (int i=0;i<2;i++)
        #pragma unroll
        for (int j=0;j<4;j++) wmma::fill_fragment(c[i][j], 0.f);

    const int NIT = K / BKK;   // 32

    // stage s tile bases (bf16 elem offsets): [s][tile] tile: 0=Ahi 1=Alo 2=Whi 3=Wlo
    auto issue_tiles = [&](int k0, int s) {
        const __nv_bfloat16* srcs[4] = { Ahi, Alo, Whi, Wlo };
        #pragma unroll
        for (int t = 0; t < 4; t++) {
            const uint32_t tb = smbase + (uint32_t)((s*4 + t)*TSTB)*2u;
            const __nv_bfloat16* src = srcs[t];
            const int r0 = (t < 2) ? m0 : n0;
            // 128 rows x 32 bf16 = 128 x 4 chunks of 16B
            #pragma unroll
            for (int idx = tid; idx < 512; idx += 256) {
                int r = idx >> 2, cg = idx & 3;   // cg: 16B chunk = 8 bf16
                cp16(tb + (uint32_t)(r*TPB + cg*8)*2u,
                     &src[(size_t)(r0+r)*K + k0 + cg*8]);
            }
        }
        asm volatile("cp.async.commit_group;");
    };

    issue_tiles(0, 0);

    for (int it = 0; it < NIT; it++) {
        const int cur = it & 1;
        if (it + 1 < NIT) {
            issue_tiles((it+1)*BKK, (it+1) & 1);
            asm volatile("cp.async.wait_group 1;");
        } else {
            asm volatile("cp.async.wait_group 0;");
        }
        __syncthreads();

        const __nv_bfloat16* At_hi = dynsmb + (cur*4 + 0)*TSTB;
        const __nv_bfloat16* At_lo = dynsmb + (cur*4 + 1)*TSTB;
        const __nv_bfloat16* Wt_hi = dynsmb + (cur*4 + 2)*TSTB;
        const __nv_bfloat16* Wt_lo = dynsmb + (cur*4 + 3)*TSTB;

        #pragma unroll
        for (int kk = 0; kk < BKK; kk += 16) {
            wmma::fragment<wmma::matrix_a,16,16,16,__nv_bfloat16,wmma::row_major> ahi[2], alo[2];
            wmma::fragment<wmma::matrix_b,16,16,16,__nv_bfloat16,wmma::col_major> bhi[4], blo[4];
            #pragma unroll
            for (int i=0;i<2;i++) {
                wmma::load_matrix_sync(ahi[i], &At_hi[(warp_m*32 + i*16)*TPB + kk], TPB);
                wmma::load_matrix_sync(alo[i], &At_lo[(warp_m*32 + i*16)*TPB + kk], TPB);
            }
            #pragma unroll
            for (int j=0;j<4;j++) {
                wmma::load_matrix_sync(bhi[j], &Wt_hi[(warp_n*64 + j*16)*TPB + kk], TPB);
                wmma::load_matrix_sync(blo[j], &Wt_lo[(warp_n*64 + j*16)*TPB + kk], TPB);
            }
            #pragma unroll
            for (int i=0;i<2;i++)
                #pragma unroll
                for (int j=0;j<4;j++) {
                    wmma::mma_sync(c[i][j], ahi[i], blo[j], c[i][j]);
                    wmma::mma_sync(c[i][j], alo[i], bhi[j], c[i][j]);
                    wmma::mma_sync(c[i][j], ahi[i], bhi[j], c[i][j]);
                }
        }
        __syncthreads();
    }

    // epilogue with bias; reuse pipeline smem as per-warp float staging [16][20]
    float* stage = reinterpret_cast<float*>(dynsmb) + w*(16*20);
    #pragma unroll
    for (int i=0;i<2;i++)
        #pragma unroll
        for (int j=0;j<4;j++) {
            wmma::store_matrix_sync(stage, c[i][j], 20, wmma::mem_row_major);
            __syncwarp();
            int gmb = m0 + warp_m*32 + i*16;
            int gnb = n0 + warp_n*64 + j*16;
            #pragma unroll
            for (int e = lane; e < 256; e += 32) {
                int r = e >> 4, cc = e & 15;
                C[(size_t)(gmb+r)*N + gnb+cc] = stage[r*20+cc] + bias[gnb+cc];
            }
            __syncwarp();
        }
}

__global__ __launch_bounds__(256) void gemm_bias_kernel(
    const __nv_bfloat16* __restrict__ Ahi, const __nv_bfloat16* __restrict__ Alo,
    const __nv_bfloat16* __restrict__ Whi, const __nv_bfloat16* __restrict__ Wlo,
    const float* __restrict__ bias, float* __restrict__ C,
    int M, int N, int K)
{
    gemm_bias_body(Ahi, Alo, Whi, Wlo, bias, C, M, N, K);
}

// Fused QKV: grid.z in {0,1,2} selects weight slice and output
__global__ __launch_bounds__(256) void gemm_qkv_kernel(
    const __nv_bfloat16* __restrict__ xhi, const __nv_bfloat16* __restrict__ xlo,
    const __nv_bfloat16* __restrict__ whi, const __nv_bfloat16* __restrict__ wlo,
    const float* __restrict__ bq, const float* __restrict__ bk, const float* __restrict__ bv,
    float* __restrict__ Qo, float* __restrict__ Ko, float* __restrict__ Vo)
{
    const int z = blockIdx.z;
    const float* bias = (z == 0) ? bq : (z == 1) ? bk : bv;
    float* C = (z == 0) ? Qo : (z == 1) ? Ko : Vo;
    gemm_bias_body(xhi, xlo, whi + (size_t)z*DD, wlo + (size_t)z*DD, bias, C, MTOT, D_, D_);
}

// ---------------------------------------------------------------------------
// Flash attention (causal), single-pass TF32 MMAs, 2 threads/row softmax
// ---------------------------------------------------------------------------
#define BR 128
#define BC 64
#define QPITCH 68

__global__ __launch_bounds__(256) void flash_kernel(
    const float* __restrict__ Q, const float* __restrict__ K,
    const float* __restrict__ V, float* __restrict__ Aout)
{
    extern __shared__ float sm[];
    float* Qsm  = sm;                      // [128][68] (pre-scaled)
    float* Ksm  = Qsm  + 128*QPITCH;       // [64][68]
    float* Vsm  = Ksm  +  64*QPITCH;       // [64][68]
    float* Ssm  = Vsm  +  64*QPITCH;       // [128][68]
    float* Osm  = Ssm  + 128*QPITCH;       // [128][64]
    float* mrow = Osm  + 128*64;           // [128]
    float* lrow = mrow + 128;              // [128]
    float* arow = lrow + 128;              // [128]

    const int tid  = threadIdx.x;
    const int w    = tid >> 5;
    const int bh   = blockIdx.y;
    const int b    = bh / H_;
    const int h    = bh % H_;
    const int qt0  = blockIdx.x * BR;
    const float scale = 0.125f;            // 1/sqrt(64)

    const size_t qbase = (size_t)(b*T_ + qt0) * D_ + h*HD_;

    #pragma unroll
    for (int idx = tid; idx < 2048; idx += 256) {
        int r = idx >> 4, cg = idx & 15;
        float4 v = *reinterpret_cast<const float4*>(&Q[qbase + (size_t)r*D_ + cg*4]);
        v.x *= scale; v.y *= scale; v.z *= scale; v.w *= scale;
        *reinterpret_cast<float4*>(&Qsm[r*QPITCH + cg*4]) = v;
    }
    if (tid < 128) { mrow[tid] = -INFINITY; lrow[tid] = 0.f; }
    for (int idx = tid; idx < 128*64; idx += 256) Osm[idx] = 0.f;
    __syncthreads();

    const int njt = qt0/BC + 2;  // causal: only key tiles up to the diagonal
    for (int j = 0; j < njt; j++) {
        const int s0 = j * BC;
        const size_t kvbase = (size_t)(b*T_ + s0) * D_ + h*HD_;
        #pragma unroll
        for (int idx = tid; idx < 2048; idx += 256) {
            int which = idx >> 10;
            int e = idx & 1023;
            int r = e >> 4, cg = e & 15;
            const float* src = which ? V : K;
            float4 v = *reinterpret_cast<const float4*>(&src[kvbase + (size_t)r*D_ + cg*4]);
            float* dst = which ? Vsm : Ksm;
            *reinterpret_cast<float4*>(&dst[r*QPITCH + cg*4]) = v;
        }
        __syncthreads();

        // S = Qs @ K^T : [128x64]; warps 4(m) x 2(n); single-pass TF32
        {
            const int wm = w >> 1, wn = w & 1;
            wmma::fragment<wmma::accumulator,16,16,8,float> cfr[2][2];
            #pragma unroll
            for (int i=0;i<2;i++)
                #pragma unroll
                for (int jj=0;jj<2;jj++) wmma::fill_fragment(cfr[i][jj], 0.f);
            #pragma unroll
            for (int kk = 0; kk < HD_; kk += 8) {
                wmma::fragment<wmma::matrix_a,16,16,8,wmma::precision::tf32,wmma::row_major> af[2];
                wmma::fragment<wmma::matrix_b,16,16,8,wmma::precision::tf32,wmma::col_major> bf[2];
                #pragma unroll
                for (int i=0;i<2;i++) {
                    wmma::load_matrix_sync(af[i], &Qsm[(wm*32+i*16)*QPITCH + kk], QPITCH);
                    cvt_frag(af[i]);
                }
                #pragma unroll
                for (int jj=0;jj<2;jj++) {
                    wmma::load_matrix_sync(bf[jj], &Ksm[(wn*32+jj*16)*QPITCH + kk], QPITCH);
                    cvt_frag(bf[jj]);
                }
                #pragma unroll
                for (int i=0;i<2;i++)
                    #pragma unroll
                    for (int jj=0;jj<2;jj++)
                        wmma::mma_sync(cfr[i][jj], af[i], bf[jj], cfr[i][jj]);
            }
            #pragma unroll
            for (int i=0;i<2;i++)
                #pragma unroll
                for (int jj=0;jj<2;jj++)
                    wmma::store_matrix_sync(&Ssm[(wm*32+i*16)*QPITCH + wn*32+jj*16],
                                            cfr[i][jj], QPITCH, wmma::mem_row_major);
        }
        __syncthreads();

        // online softmax: 2 threads per row (halves combined via shfl_xor 1)
        {
            const int r = tid >> 1, half = tid & 1;
            const int qrow = qt0 + r;
            const float mold = mrow[r];
            int clim = qrow - s0;            // valid cols c <= clim (may be <0)
            if (clim > BC-1) clim = BC-1;
            const int c0 = half*32;
            float mt = -INFINITY;
            #pragma unroll
            for (int c = c0; c < c0+32; c++)
                if (c <= clim) mt = fmaxf(mt, Ssm[r*QPITCH+c]);
            mt = fmaxf(mt, __shfl_xor_sync(0xffffffffu, mt, 1));
            const float mnew = fmaxf(mold, mt);
            const float alpha = __expf(mold - mnew);   // mold=-inf first tile -> 0
            float lsum = 0.f;
            #pragma unroll
            for (int c = c0; c < c0+32; c++) {
                float p = (c <= clim) ? __expf(Ssm[r*QPITCH+c] - mnew) : 0.f;
                Ssm[r*QPITCH+c] = p;
                lsum += p;
            }
            lsum += __shfl_xor_sync(0xffffffffu, lsum, 1);
            if (half == 0) {
                mrow[r] = mnew;
                lrow[r] = lrow[r]*alpha + lsum;
                arow[r] = alpha;
            }
        }
        __syncthreads();

        // PV = P @ V : each warp 16 rows x 64 cols; single-pass TF32
        {
            wmma::fragment<wmma::accumulator,16,16,8,float> pv[4];
            #pragma unroll
            for (int jj=0;jj<4;jj++) wmma::fill_fragment(pv[jj], 0.f);
            #pragma unroll
            for (int kk = 0; kk < BC; kk += 8) {
                wmma::fragment<wmma::matrix_a,16,16,8,wmma::precision::tf32,wmma::row_major> af;
                wmma::load_matrix_sync(af, &Ssm[(w*16)*QPITCH + kk], QPITCH);
                cvt_frag(af);
                wmma::fragment<wmma::matrix_b,16,16,8,wmma::precision::tf32,wmma::row_major> bf[4];
                #pragma unroll
                for (int jj=0;jj<4;jj++) {
                    wmma::load_matrix_sync(bf[jj], &Vsm[kk*QPITCH + jj*16], QPITCH);
                    cvt_frag(bf[jj]);
                }
                #pragma unroll
                for (int jj=0;jj<4;jj++) wmma::mma_sync(pv[jj], af, bf[jj], pv[jj]);
            }
            #pragma unroll
            for (int jj=0;jj<4;jj++)
                wmma::store_matrix_sync(&Ssm[(w*16)*QPITCH + jj*16], pv[jj], QPITCH,
                                        wmma::mem_row_major);
        }
        __syncthreads();

        // O = O*alpha + PV
        {
            const int r = tid >> 1, half = tid & 1;
            const float alpha = arow[r];
            #pragma unroll
            for (int c = half*32; c < half*32+32; c++)
                Osm[r*64+c] = Osm[r*64+c]*alpha + Ssm[r*QPITCH+c];
        }
        __syncthreads();
    }

    // epilogue: normalize and write attention output (canonical layout)
    {
        const size_t obase = (size_t)(b*T_ + qt0) * D_ + h*HD_;
        for (int idx = tid; idx < 128*64; idx += 256) {
            int r = idx >> 6, c = idx & 63;
            Aout[obase + (size_t)r*D_ + c] = Osm[r*64+c] / lrow[r];
        }
    }
}

// ---------------------------------------------------------------------------
// Launch
// ---------------------------------------------------------------------------
static const int FLASH_SMEM =
    (128*QPITCH + 64*QPITCH + 64*QPITCH + 128*QPITCH + 128*64 + 3*128) * (int)sizeof(float);

extern "C" void kernel_launch(void* const* d_in, const int* in_sizes, int n_in,
                              void* d_out, int out_size)
{
    const float* x  = (const float*)d_in[0];
    const float* wq = (const float*)d_in[1];
    const float* bq = (const float*)d_in[2];
    const float* wk = (const float*)d_in[3];
    const float* bk = (const float*)d_in[4];
    const float* wv = (const float*)d_in[5];
    const float* bv = (const float*)d_in[6];
    const float* wo = (const float*)d_in[7];
    const float* bo = (const float*)d_in[8];
    // d_in[9] is the causal mask; causality is applied analytically in flash_kernel.
    float* out = (float*)d_out;

    float *qb, *kb, *vb, *ab;
    __nv_bfloat16 *xhi, *xlo, *ahi, *alo, *whi, *wlo;
    cudaGetSymbolAddress((void**)&qb, g_Q);
    cudaGetSymbolAddress((void**)&kb, g_K);
    cudaGetSymbolAddress((void**)&vb, g_V);
    cudaGetSymbolAddress((void**)&ab, g_A);
    cudaGetSymbolAddress((void**)&xhi, g_xhi);
    cudaGetSymbolAddress((void**)&xlo, g_xlo);
    cudaGetSymbolAddress((void**)&ahi, g_ahi);
    cudaGetSymbolAddress((void**)&alo, g_alo);
    cudaGetSymbolAddress((void**)&whi, g_whi);
    cudaGetSymbolAddress((void**)&wlo, g_wlo);

    cudaFuncSetAttribute(flash_kernel, cudaFuncAttributeMaxDynamicSharedMemorySize, FLASH_SMEM);
    cudaFuncSetAttribute(gemm_qkv_kernel, cudaFuncAttributeMaxDynamicSharedMemorySize, GEMM_DSMEM);
    cudaFuncSetAttribute(gemm_bias_kernel, cudaFuncAttributeMaxDynamicSharedMemorySize, GEMM_DSMEM);

    // split inputs into bf16 hi/lo
    split_kernel<<<512, 256>>>(x,  xhi, xlo, MTOT*D_);
    split_kernel<<<128, 256>>>(wq, whi + 0*(size_t)DD, wlo + 0*(size_t)DD, DD);
    split_kernel<<<128, 256>>>(wk, whi + 1*(size_t)DD, wlo + 1*(size_t)DD, DD);
    split_kernel<<<128, 256>>>(wv, whi + 2*(size_t)DD, wlo + 2*(size_t)DD, DD);
    split_kernel<<<128, 256>>>(wo, whi + 3*(size_t)DD, wlo + 3*(size_t)DD, DD);

    dim3 qkv_grid(MTOT/BM, D_/BN, 3);   // (64, 8, 3)
    gemm_qkv_kernel<<<qkv_grid, 256, GEMM_DSMEM>>>(xhi, xlo, whi, wlo, bq, bk, bv, qb, kb, vb);

    dim3 flash_grid(T_/BR, B_*H_);      // (16, 64)
    flash_kernel<<<flash_grid, 256, FLASH_SMEM>>>(qb, kb, vb, ab);

    split_kernel<<<512, 256>>>(ab, ahi, alo, MTOT*D_);

    dim3 gemm_grid(MTOT/BM, D_/BN);     // (64, 8)
    gemm_bias_kernel<<<gemm_grid, 256, GEMM_DSMEM>>>(ahi, alo, whi + 3*(size_t)DD, wlo + 3*(size_t)DD,
                                                     bo, out, MTOT, D_, D_);
}

// round 13
// speedup vs baseline: 2.6596x; 1.3081x over previous
#include <cuda_runtime.h>
#include <cstdint>
#include <cuda_bf16.h>
#include <mma.h>
#include <math.h>

using namespace nvcuda;

#define B_  4
#define T_  2048
#define D_  1024
#define H_  16
#define HD_ 64
#define MTOT (B_*T_)   // 8192
#define DD  (D_*D_)    // 1048576

// Scratch (device globals: allocation-free rule)
__device__ float g_Q[MTOT*D_];
__device__ float g_K[MTOT*D_];
__device__ float g_V[MTOT*D_];
__device__ float g_A[MTOT*D_];
// bf16 hi/lo split operands
__device__ __nv_bfloat16 g_xhi[MTOT*D_];
__device__ __nv_bfloat16 g_xlo[MTOT*D_];
__device__ __nv_bfloat16 g_ahi[MTOT*D_];
__device__ __nv_bfloat16 g_alo[MTOT*D_];
__device__ __nv_bfloat16 g_whi[4*DD];   // wq, wk, wv, wo
__device__ __nv_bfloat16 g_wlo[4*DD];

// ---------------------------------------------------------------------------
// Split fp32 -> bf16 hi + bf16 lo
// ---------------------------------------------------------------------------
__device__ __forceinline__ void split_body(
    const float* __restrict__ src, __nv_bfloat16* __restrict__ hi,
    __nv_bfloat16* __restrict__ lo, int n)
{
    int i = blockIdx.x*blockDim.x + threadIdx.x;
    int stride = gridDim.x*blockDim.x;
    for (; i < n/4; i += stride) {
        float4 v = reinterpret_cast<const float4*>(src)[i];
        __nv_bfloat16 h0 = __float2bfloat16(v.x);
        __nv_bfloat16 h1 = __float2bfloat16(v.y);
        __nv_bfloat16 h2 = __float2bfloat16(v.z);
        __nv_bfloat16 h3 = __float2bfloat16(v.w);
        __nv_bfloat162 hA; hA.x = h0; hA.y = h1;
        __nv_bfloat162 hB; hB.x = h2; hB.y = h3;
        __nv_bfloat162 lA, lB;
        lA.x = __float2bfloat16(v.x - __bfloat162float(h0));
        lA.y = __float2bfloat16(v.y - __bfloat162float(h1));
        lB.x = __float2bfloat16(v.z - __bfloat162float(h2));
        lB.y = __float2bfloat16(v.w - __bfloat162float(h3));
        reinterpret_cast<__nv_bfloat162*>(hi)[i*2+0] = hA;
        reinterpret_cast<__nv_bfloat162*>(hi)[i*2+1] = hB;
        reinterpret_cast<__nv_bfloat162*>(lo)[i*2+0] = lA;
        reinterpret_cast<__nv_bfloat162*>(lo)[i*2+1] = lB;
    }
}

__global__ __launch_bounds__(256) void split_kernel(
    const float* __restrict__ src, __nv_bfloat16* __restrict__ hi,
    __nv_bfloat16* __restrict__ lo, int n)
{
    split_body(src, hi, lo, n);
}

// All 4 weight splits in one launch: grid.z selects the weight
__global__ __launch_bounds__(256) void split_w_kernel(
    const float* __restrict__ wq, const float* __restrict__ wk,
    const float* __restrict__ wv, const float* __restrict__ wo,
    __nv_bfloat16* __restrict__ whi, __nv_bfloat16* __restrict__ wlo)
{
    const int z = blockIdx.z;
    const float* src = (z==0) ? wq : (z==1) ? wk : (z==2) ? wv : wo;
    split_body(src, whi + (size_t)z*DD, wlo + (size_t)z*DD, DD);
}

__device__ __forceinline__ void cp16(uint32_t saddr, const void* g) {
    asm volatile("cp.async.cg.shared.global [%0], [%1], 16;" :: "r"(saddr), "l"(g));
}

template <typename FragT>
__device__ __forceinline__ void cvt_frag(FragT& f) {
    #pragma unroll
    for (int e = 0; e < f.num_elements; e++) f.x[e] = wmma::__float_to_tf32(f.x[e]);
}

// ---------------------------------------------------------------------------
// GEMM: C[M,N] = A[M,K] @ W[N,K]^T + bias, bf16x3, 2-stage cp.async pipeline
// A/W pre-split into bf16 hi/lo. BM=128 BN=128 BK=32, k=16 per MMA. 2 CTAs/SM.
// ---------------------------------------------------------------------------
#define BM 128
#define BN 128
#define BKK 32
#define TPB 40                       // bf16 tile row pitch (80 bytes)
#define TSTB (128*TPB)               // bf16 elems per tile
static const int GEMM_DSMEM = (8*TSTB) * (int)sizeof(__nv_bfloat16);   // 81920 B

__device__ __forceinline__ void gemm_bias_body(
    const __nv_bfloat16* __restrict__ Ahi, const __nv_bfloat16* __restrict__ Alo,
    const __nv_bfloat16* __restrict__ Whi, const __nv_bfloat16* __restrict__ Wlo,
    const float* __restrict__ bias, float* __restrict__ C,
    int M, int N, int K)
{
    extern __shared__ __nv_bfloat16 dynsmb[];
    const uint32_t smbase = (uint32_t)__cvta_generic_to_shared(dynsmb);

    const int tid  = threadIdx.x;
    const int w    = tid >> 5;
    const int lane = tid & 31;
    const int warp_m = w >> 1;           // 0..3
    const int warp_n = w & 1;            // 0..1
    const int m0 = blockIdx.x * BM;
    const int n0 = blockIdx.y * BN;

    wmma::fragment<wmma::accumulator,16,16,16,float> c[2][4];
    #pragma unroll
    for (int i=0;i<2;i++)
        #pragma unroll
        for (int j=0;j<4;j++) wmma::fill_fragment(c[i][j], 0.f);

    const int NIT = K / BKK;   // 32

    auto issue_tiles = [&](int k0, int s) {
        const __nv_bfloat16* srcs[4] = { Ahi, Alo, Whi, Wlo };
        #pragma unroll
        for (int t = 0; t < 4; t++) {
            const uint32_t tb = smbase + (uint32_t)((s*4 + t)*TSTB)*2u;
            const __nv_bfloat16* src = srcs[t];
            const int r0 = (t < 2) ? m0 : n0;
            #pragma unroll
            for (int idx = tid; idx < 512; idx += 256) {
                int r = idx >> 2, cg = idx & 3;   // 16B chunk = 8 bf16
                cp16(tb + (uint32_t)(r*TPB + cg*8)*2u,
                     &src[(size_t)(r0+r)*K + k0 + cg*8]);
            }
        }
        asm volatile("cp.async.commit_group;");
    };

    issue_tiles(0, 0);

    for (int it = 0; it < NIT; it++) {
        const int cur = it & 1;
        if (it + 1 < NIT) {
            issue_tiles((it+1)*BKK, (it+1) & 1);
            asm volatile("cp.async.wait_group 1;");
        } else {
            asm volatile("cp.async.wait_group 0;");
        }
        __syncthreads();

        const __nv_bfloat16* At_hi = dynsmb + (cur*4 + 0)*TSTB;
        const __nv_bfloat16* At_lo = dynsmb + (cur*4 + 1)*TSTB;
        const __nv_bfloat16* Wt_hi = dynsmb + (cur*4 + 2)*TSTB;
        const __nv_bfloat16* Wt_lo = dynsmb + (cur*4 + 3)*TSTB;

        #pragma unroll
        for (int kk = 0; kk < BKK; kk += 16) {
            wmma::fragment<wmma::matrix_a,16,16,16,__nv_bfloat16,wmma::row_major> ahi[2], alo[2];
            wmma::fragment<wmma::matrix_b,16,16,16,__nv_bfloat16,wmma::col_major> bhi[4], blo[4];
            #pragma unroll
            for (int i=0;i<2;i++) {
                wmma::load_matrix_sync(ahi[i], &At_hi[(warp_m*32 + i*16)*TPB + kk], TPB);
                wmma::load_matrix_sync(alo[i], &At_lo[(warp_m*32 + i*16)*TPB + kk], TPB);
            }
            #pragma unroll
            for (int j=0;j<4;j++) {
                wmma::load_matrix_sync(bhi[j], &Wt_hi[(warp_n*64 + j*16)*TPB + kk], TPB);
                wmma::load_matrix_sync(blo[j], &Wt_lo[(warp_n*64 + j*16)*TPB + kk], TPB);
            }
            #pragma unroll
            for (int i=0;i<2;i++)
                #pragma unroll
                for (int j=0;j<4;j++) {
                    wmma::mma_sync(c[i][j], ahi[i], blo[j], c[i][j]);
                    wmma::mma_sync(c[i][j], alo[i], bhi[j], c[i][j]);
                    wmma::mma_sync(c[i][j], ahi[i], bhi[j], c[i][j]);
                }
        }
        __syncthreads();
    }

    // epilogue with bias; reuse pipeline smem as per-warp float staging [16][20]
    float* stage = reinterpret_cast<float*>(dynsmb) + w*(16*20);
    #pragma unroll
    for (int i=0;i<2;i++)
        #pragma unroll
        for (int j=0;j<4;j++) {
            wmma::store_matrix_sync(stage, c[i][j], 20, wmma::mem_row_major);
            __syncwarp();
            int gmb = m0 + warp_m*32 + i*16;
            int gnb = n0 + warp_n*64 + j*16;
            #pragma unroll
            for (int e = lane; e < 256; e += 32) {
                int r = e >> 4, cc = e & 15;
                C[(size_t)(gmb+r)*N + gnb+cc] = stage[r*20+cc] + bias[gnb+cc];
            }
            __syncwarp();
        }
}

__global__ __launch_bounds__(256,2) void gemm_bias_kernel(
    const __nv_bfloat16* __restrict__ Ahi, const __nv_bfloat16* __restrict__ Alo,
    const __nv_bfloat16* __restrict__ Whi, const __nv_bfloat16* __restrict__ Wlo,
    const float* __restrict__ bias, float* __restrict__ C,
    int M, int N, int K)
{
    gemm_bias_body(Ahi, Alo, Whi, Wlo, bias, C, M, N, K);
}

// Fused QKV: grid.z in {0,1,2} selects weight slice and output
__global__ __launch_bounds__(256,2) void gemm_qkv_kernel(
    const __nv_bfloat16* __restrict__ xhi, const __nv_bfloat16* __restrict__ xlo,
    const __nv_bfloat16* __restrict__ whi, const __nv_bfloat16* __restrict__ wlo,
    const float* __restrict__ bq, const float* __restrict__ bk, const float* __restrict__ bv,
    float* __restrict__ Qo, float* __restrict__ Ko, float* __restrict__ Vo)
{
    const int z = blockIdx.z;
    const float* bias = (z == 0) ? bq : (z == 1) ? bk : bv;
    float* C = (z == 0) ? Qo : (z == 1) ? Ko : Vo;
    gemm_bias_body(xhi, xlo, whi + (size_t)z*DD, wlo + (size_t)z*DD, bias, C, MTOT, D_, D_);
}

// ---------------------------------------------------------------------------
// Flash attention (causal), single-pass TF32, BR=64 for 2 CTAs/SM.
// PV writes to a SEPARATE buffer Psm (fixes the R12 cross-warp race).
// ---------------------------------------------------------------------------
#define BR 64
#define BC 64
#define QPITCH 68

__global__ __launch_bounds__(256,2) void flash_kernel(
    const float* __restrict__ Q, const float* __restrict__ K,
    const float* __restrict__ V, float* __restrict__ Aout)
{
    extern __shared__ float sm[];
    float* Qsm  = sm;                      // [64][68] (pre-scaled)
    float* Ksm  = Qsm  + 64*QPITCH;        // [64][68]
    float* Vsm  = Ksm  + 64*QPITCH;        // [64][68]
    float* Ssm  = Vsm  + 64*QPITCH;        // [64][68]  S then P
    float* Psm  = Ssm  + 64*QPITCH;        // [64][68]  PV output (separate!)
    float* Osm  = Psm  + 64*QPITCH;        // [64][64]
    float* mrow = Osm  + 64*64;            // [64]
    float* lrow = mrow + 64;               // [64]
    float* arow = lrow + 64;               // [64]

    const int tid  = threadIdx.x;
    const int w    = tid >> 5;
    const int wm   = w >> 1;               // 0..3 (rows)
    const int wn   = w & 1;                // 0..1 (cols)
    const int bh   = blockIdx.y;
    const int b    = bh / H_;
    const int h    = bh % H_;
    // heavy CTAs (large bx) first: reverse mapping
    const int bx   = (int)gridDim.x - 1 - (int)blockIdx.x;
    const int qt0  = bx * BR;
    const float scale = 0.125f;            // 1/sqrt(64)

    const size_t qbase = (size_t)(b*T_ + qt0) * D_ + h*HD_;

    // load Q tile (scaled): 64x64 = 1024 float4
    #pragma unroll
    for (int idx = tid; idx < 1024; idx += 256) {
        int r = idx >> 4, cg = idx & 15;
        float4 v = *reinterpret_cast<const float4*>(&Q[qbase + (size_t)r*D_ + cg*4]);
        v.x *= scale; v.y *= scale; v.z *= scale; v.w *= scale;
        *reinterpret_cast<float4*>(&Qsm[r*QPITCH + cg*4]) = v;
    }
    if (tid < 64) { mrow[tid] = -INFINITY; lrow[tid] = 0.f; }
    for (int idx = tid; idx < 64*64; idx += 256) Osm[idx] = 0.f;
    __syncthreads();

    const int njt = bx + 1;  // causal: key tiles 0..bx
    for (int j = 0; j < njt; j++) {
        const int s0 = j * BC;
        const size_t kvbase = (size_t)(b*T_ + s0) * D_ + h*HD_;
        #pragma unroll
        for (int idx = tid; idx < 2048; idx += 256) {
            int which = idx >> 10;
            int e = idx & 1023;
            int r = e >> 4, cg = e & 15;
            const float* src = which ? V : K;
            float4 v = *reinterpret_cast<const float4*>(&src[kvbase + (size_t)r*D_ + cg*4]);
            float* dst = which ? Vsm : Ksm;
            *reinterpret_cast<float4*>(&dst[r*QPITCH + cg*4]) = v;
        }
        __syncthreads();

        // S = Qs @ K^T : [64x64]; warps 4(m) x 2(n), each 16x32; TF32
        {
            wmma::fragment<wmma::accumulator,16,16,8,float> cfr[2];
            #pragma unroll
            for (int jj=0;jj<2;jj++) wmma::fill_fragment(cfr[jj], 0.f);
            #pragma unroll
            for (int kk = 0; kk < HD_; kk += 8) {
                wmma::fragment<wmma::matrix_a,16,16,8,wmma::precision::tf32,wmma::row_major> af;
                wmma::fragment<wmma::matrix_b,16,16,8,wmma::precision::tf32,wmma::col_major> bf[2];
                wmma::load_matrix_sync(af, &Qsm[(wm*16)*QPITCH + kk], QPITCH);
                cvt_frag(af);
                #pragma unroll
                for (int jj=0;jj<2;jj++) {
                    wmma::load_matrix_sync(bf[jj], &Ksm[(wn*32+jj*16)*QPITCH + kk], QPITCH);
                    cvt_frag(bf[jj]);
                }
                #pragma unroll
                for (int jj=0;jj<2;jj++)
                    wmma::mma_sync(cfr[jj], af, bf[jj], cfr[jj]);
            }
            #pragma unroll
            for (int jj=0;jj<2;jj++)
                wmma::store_matrix_sync(&Ssm[(wm*16)*QPITCH + wn*32+jj*16],
                                        cfr[jj], QPITCH, wmma::mem_row_major);
        }
        __syncthreads();

        // online softmax: 4 threads per row (combine via shfl_xor 1,2)
        {
            const int r = tid >> 2, quad = tid & 3;
            const int qrow = qt0 + r;
            const float mold = mrow[r];
            int clim = qrow - s0;            // valid cols c <= clim
            if (clim > BC-1) clim = BC-1;
            const int c0 = quad*16;
            float mt = -INFINITY;
            #pragma unroll
            for (int c = c0; c < c0+16; c++)
                if (c <= clim) mt = fmaxf(mt, Ssm[r*QPITCH+c]);
            mt = fmaxf(mt, __shfl_xor_sync(0xffffffffu, mt, 1));
            mt = fmaxf(mt, __shfl_xor_sync(0xffffffffu, mt, 2));
            const float mnew = fmaxf(mold, mt);
            const float alpha = __expf(mold - mnew);   // mold=-inf first tile -> 0
            float lsum = 0.f;
            #pragma unroll
            for (int c = c0; c < c0+16; c++) {
                float p = (c <= clim) ? __expf(Ssm[r*QPITCH+c] - mnew) : 0.f;
                Ssm[r*QPITCH+c] = p;
                lsum += p;
            }
            lsum += __shfl_xor_sync(0xffffffffu, lsum, 1);
            lsum += __shfl_xor_sync(0xffffffffu, lsum, 2);
            if (quad == 0) {
                mrow[r] = mnew;
                lrow[r] = lrow[r]*alpha + lsum;
                arow[r] = alpha;
            }
        }
        __syncthreads();

        // PV = P @ V : warps 4(m) x 2(n), each 16 rows x 32 cols; TF32
        // Output goes to Psm (NOT Ssm) — P stays intact while all warps read it.
        {
            wmma::fragment<wmma::accumulator,16,16,8,float> pv[2];
            #pragma unroll
            for (int jj=0;jj<2;jj++) wmma::fill_fragment(pv[jj], 0.f);
            #pragma unroll
            for (int kk = 0; kk < BC; kk += 8) {
                wmma::fragment<wmma::matrix_a,16,16,8,wmma::precision::tf32,wmma::row_major> af;
                wmma::load_matrix_sync(af, &Ssm[(wm*16)*QPITCH + kk], QPITCH);
                cvt_frag(af);
                wmma::fragment<wmma::matrix_b,16,16,8,wmma::precision::tf32,wmma::row_major> bf[2];
                #pragma unroll
                for (int jj=0;jj<2;jj++) {
                    wmma::load_matrix_sync(bf[jj], &Vsm[kk*QPITCH + wn*32 + jj*16], QPITCH);
                    cvt_frag(bf[jj]);
                }
                #pragma unroll
                for (int jj=0;jj<2;jj++) wmma::mma_sync(pv[jj], af, bf[jj], pv[jj]);
            }
            #pragma unroll
            for (int jj=0;jj<2;jj++)
                wmma::store_matrix_sync(&Psm[(wm*16)*QPITCH + wn*32 + jj*16], pv[jj], QPITCH,
                                        wmma::mem_row_major);
        }
        __syncthreads();

        // O = O*alpha + PV
        {
            const int r = tid >> 2, quad = tid & 3;
            const float alpha = arow[r];
            #pragma unroll
            for (int c = quad*16; c < quad*16+16; c++)
                Osm[r*64+c] = Osm[r*64+c]*alpha + Psm[r*QPITCH+c];
        }
        __syncthreads();
    }

    // epilogue: normalize and write attention output (canonical layout)
    {
        const size_t obase = (size_t)(b*T_ + qt0) * D_ + h*HD_;
        for (int idx = tid; idx < 64*64; idx += 256) {
            int r = idx >> 6, c = idx & 63;
            Aout[obase + (size_t)r*D_ + c] = Osm[r*64+c] / lrow[r];
        }
    }
}

// ---------------------------------------------------------------------------
// Launch
// ---------------------------------------------------------------------------
static const int FLASH_SMEM =
    (5*64*QPITCH + 64*64 + 3*64) * (int)sizeof(float);   // 104,192 B

extern "C" void kernel_launch(void* const* d_in, const int* in_sizes, int n_in,
                              void* d_out, int out_size)
{
    const float* x  = (const float*)d_in[0];
    const float* wq = (const float*)d_in[1];
    const float* bq = (const float*)d_in[2];
    const float* wk = (const float*)d_in[3];
    const float* bk = (const float*)d_in[4];
    const float* wv = (const float*)d_in[5];
    const float* bv = (const float*)d_in[6];
    const float* wo = (const float*)d_in[7];
    const float* bo = (const float*)d_in[8];
    // d_in[9] is the causal mask; causality is applied analytically in flash_kernel.
    float* out = (float*)d_out;

    float *qb, *kb, *vb, *ab;
    __nv_bfloat16 *xhi, *xlo, *ahi, *alo, *whi, *wlo;
    cudaGetSymbolAddress((void**)&qb, g_Q);
    cudaGetSymbolAddress((void**)&kb, g_K);
    cudaGetSymbolAddress((void**)&vb, g_V);
    cudaGetSymbolAddress((void**)&ab, g_A);
    cudaGetSymbolAddress((void**)&xhi, g_xhi);
    cudaGetSymbolAddress((void**)&xlo, g_xlo);
    cudaGetSymbolAddress((void**)&ahi, g_ahi);
    cudaGetSymbolAddress((void**)&alo, g_alo);
    cudaGetSymbolAddress((void**)&whi, g_whi);
    cudaGetSymbolAddress((void**)&wlo, g_wlo);

    cudaFuncSetAttribute(flash_kernel, cudaFuncAttributeMaxDynamicSharedMemorySize, FLASH_SMEM);
    cudaFuncSetAttribute(gemm_qkv_kernel, cudaFuncAttributeMaxDynamicSharedMemorySize, GEMM_DSMEM);
    cudaFuncSetAttribute(gemm_bias_kernel, cudaFuncAttributeMaxDynamicSharedMemorySize, GEMM_DSMEM);

    // split inputs into bf16 hi/lo
    split_kernel<<<512, 256>>>(x, xhi, xlo, MTOT*D_);
    dim3 wsplit_grid(128, 1, 4);
    split_w_kernel<<<wsplit_grid, 256>>>(wq, wk, wv, wo, whi, wlo);

    dim3 qkv_grid(MTOT/BM, D_/BN, 3);   // (64, 8, 3)
    gemm_qkv_kernel<<<qkv_grid, 256, GEMM_DSMEM>>>(xhi, xlo, whi, wlo, bq, bk, bv, qb, kb, vb);

    dim3 flash_grid(T_/BR, B_*H_);      // (32, 64)
    flash_kernel<<<flash_grid, 256, FLASH_SMEM>>>(qb, kb, vb, ab);

    split_kernel<<<512, 256>>>(ab, ahi, alo, MTOT*D_);

    dim3 gemm_grid(MTOT/BM, D_/BN);     // (64, 8)
    gemm_bias_kernel<<<gemm_grid, 256, GEMM_DSMEM>>>(ahi, alo, whi + 3*(size_t)DD, wlo + 3*(size_t)DD,
                                                     bo, out, MTOT, D_, D_);
}

// round 16
// speedup vs baseline: 3.5670x; 1.3412x over previous
#include <cuda_runtime.h>
#include <cstdint>
#include <cuda_bf16.h>
#include <mma.h>
#include <math.h>

using namespace nvcuda;

#define B_  4
#define T_  2048
#define D_  1024
#define H_  16
#define HD_ 64
#define MTOT (B_*T_)   // 8192
#define DD  (D_*D_)    // 1048576

// Scratch (device globals: allocation-free rule)
__device__ float g_Q[MTOT*D_];
__device__ float g_K[MTOT*D_];
__device__ float g_V[MTOT*D_];
__device__ float g_A[MTOT*D_];
// bf16 hi/lo split operands
__device__ __nv_bfloat16 g_xhi[MTOT*D_];
__device__ __nv_bfloat16 g_xlo[MTOT*D_];
__device__ __nv_bfloat16 g_ahi[MTOT*D_];
__device__ __nv_bfloat16 g_alo[MTOT*D_];
__device__ __nv_bfloat16 g_whi[4*DD];   // wq, wk, wv, wo
__device__ __nv_bfloat16 g_wlo[4*DD];

// ---------------------------------------------------------------------------
// Split fp32 -> bf16 hi + bf16 lo
// ---------------------------------------------------------------------------
__device__ __forceinline__ void split_body(
    const float* __restrict__ src, __nv_bfloat16* __restrict__ hi,
    __nv_bfloat16* __restrict__ lo, int n)
{
    int i = blockIdx.x*blockDim.x + threadIdx.x;
    int stride = gridDim.x*blockDim.x;
    for (; i < n/4; i += stride) {
        float4 v = reinterpret_cast<const float4*>(src)[i];
        __nv_bfloat16 h0 = __float2bfloat16(v.x);
        __nv_bfloat16 h1 = __float2bfloat16(v.y);
        __nv_bfloat16 h2 = __float2bfloat16(v.z);
        __nv_bfloat16 h3 = __float2bfloat16(v.w);
        __nv_bfloat162 hA; hA.x = h0; hA.y = h1;
        __nv_bfloat162 hB; hB.x = h2; hB.y = h3;
        __nv_bfloat162 lA, lB;
        lA.x = __float2bfloat16(v.x - __bfloat162float(h0));
        lA.y = __float2bfloat16(v.y - __bfloat162float(h1));
        lB.x = __float2bfloat16(v.z - __bfloat162float(h2));
        lB.y = __float2bfloat16(v.w - __bfloat162float(h3));
        reinterpret_cast<__nv_bfloat162*>(hi)[i*2+0] = hA;
        reinterpret_cast<__nv_bfloat162*>(hi)[i*2+1] = hB;
        reinterpret_cast<__nv_bfloat162*>(lo)[i*2+0] = lA;
        reinterpret_cast<__nv_bfloat162*>(lo)[i*2+1] = lB;
    }
}

__global__ __launch_bounds__(256) void split_kernel(
    const float* __restrict__ src, __nv_bfloat16* __restrict__ hi,
    __nv_bfloat16* __restrict__ lo, int n)
{
    split_body(src, hi, lo, n);
}

// All 4 weight splits in one launch: grid.z selects the weight
__global__ __launch_bounds__(256) void split_w_kernel(
    const float* __restrict__ wq, const float* __restrict__ wk,
    const float* __restrict__ wv, const float* __restrict__ wo,
    __nv_bfloat16* __restrict__ whi, __nv_bfloat16* __restrict__ wlo)
{
    const int z = blockIdx.z;
    const float* src = (z==0) ? wq : (z==1) ? wk : (z==2) ? wv : wo;
    split_body(src, whi + (size_t)z*DD, wlo + (size_t)z*DD, DD);
}

__device__ __forceinline__ void cp16(uint32_t saddr, const void* g) {
    asm volatile("cp.async.cg.shared.global [%0], [%1], 16;" :: "r"(saddr), "l"(g));
}

// ---------------------------------------------------------------------------
// GEMM: C[M,N] = A[M,K] @ W[N,K]^T + bias, bf16x3, 2-stage cp.async pipeline
// RND: round output to tf32 (for Q/K/V feeding the tf32 flash kernel).
// ---------------------------------------------------------------------------
#define BM 128
#define BN 128
#define BKK 32
#define TPB 40                       // bf16 tile row pitch (80 bytes)
#define TSTB (128*TPB)               // bf16 elems per tile
static const int GEMM_DSMEM = (8*TSTB) * (int)sizeof(__nv_bfloat16);   // 81920 B

template <bool RND>
__device__ __forceinline__ void gemm_bias_body(
    const __nv_bfloat16* __restrict__ Ahi, const __nv_bfloat16* __restrict__ Alo,
    const __nv_bfloat16* __restrict__ Whi, const __nv_bfloat16* __restrict__ Wlo,
    const float* __restrict__ bias, float* __restrict__ C,
    int M, int N, int K)
{
    extern __shared__ __nv_bfloat16 dynsmb[];
    const uint32_t smbase = (uint32_t)__cvta_generic_to_shared(dynsmb);

    const int tid  = threadIdx.x;
    const int w    = tid >> 5;
    const int lane = tid & 31;
    const int warp_m = w >> 1;           // 0..3
    const int warp_n = w & 1;            // 0..1
    const int m0 = blockIdx.x * BM;
    const int n0 = blockIdx.y * BN;

    wmma::fragment<wmma::accumulator,16,16,16,float> c[2][4];
    #pragma unroll
    for (int i=0;i<2;i++)
        #pragma unroll
        for (int j=0;j<4;j++) wmma::fill_fragment(c[i][j], 0.f);

    const int NIT = K / BKK;   // 32

    auto issue_tiles = [&](int k0, int s) {
        const __nv_bfloat16* srcs[4] = { Ahi, Alo, Whi, Wlo };
        #pragma unroll
        for (int t = 0; t < 4; t++) {
            const uint32_t tb = smbase + (uint32_t)((s*4 + t)*TSTB)*2u;
            const __nv_bfloat16* src = srcs[t];
            const int r0 = (t < 2) ? m0 : n0;
            #pragma unroll
            for (int idx = tid; idx < 512; idx += 256) {
                int r = idx >> 2, cg = idx & 3;   // 16B chunk = 8 bf16
                cp16(tb + (uint32_t)(r*TPB + cg*8)*2u,
                     &src[(size_t)(r0+r)*K + k0 + cg*8]);
            }
        }
        asm volatile("cp.async.commit_group;");
    };

    issue_tiles(0, 0);

    for (int it = 0; it < NIT; it++) {
        const int cur = it & 1;
        if (it + 1 < NIT) {
            issue_tiles((it+1)*BKK, (it+1) & 1);
            asm volatile("cp.async.wait_group 1;");
        } else {
            asm volatile("cp.async.wait_group 0;");
        }
        __syncthreads();

        const __nv_bfloat16* At_hi = dynsmb + (cur*4 + 0)*TSTB;
        const __nv_bfloat16* At_lo = dynsmb + (cur*4 + 1)*TSTB;
        const __nv_bfloat16* Wt_hi = dynsmb + (cur*4 + 2)*TSTB;
        const __nv_bfloat16* Wt_lo = dynsmb + (cur*4 + 3)*TSTB;

        #pragma unroll
        for (int kk = 0; kk < BKK; kk += 16) {
            wmma::fragment<wmma::matrix_a,16,16,16,__nv_bfloat16,wmma::row_major> ahi[2], alo[2];
            wmma::fragment<wmma::matrix_b,16,16,16,__nv_bfloat16,wmma::col_major> bhi[4], blo[4];
            #pragma unroll
            for (int i=0;i<2;i++) {
                wmma::load_matrix_sync(ahi[i], &At_hi[(warp_m*32 + i*16)*TPB + kk], TPB);
                wmma::load_matrix_sync(alo[i], &At_lo[(warp_m*32 + i*16)*TPB + kk], TPB);
            }
            #pragma unroll
            for (int j=0;j<4;j++) {
                wmma::load_matrix_sync(bhi[j], &Wt_hi[(warp_n*64 + j*16)*TPB + kk], TPB);
                wmma::load_matrix_sync(blo[j], &Wt_lo[(warp_n*64 + j*16)*TPB + kk], TPB);
            }
            #pragma unroll
            for (int i=0;i<2;i++)
                #pragma unroll
                for (int j=0;j<4;j++) {
                    wmma::mma_sync(c[i][j], ahi[i], blo[j], c[i][j]);
                    wmma::mma_sync(c[i][j], alo[i], bhi[j], c[i][j]);
                    wmma::mma_sync(c[i][j], ahi[i], bhi[j], c[i][j]);
                }
        }
        __syncthreads();
    }

    // epilogue with bias; reuse pipeline smem as per-warp float staging [16][20]
    float* stage = reinterpret_cast<float*>(dynsmb) + w*(16*20);
    #pragma unroll
    for (int i=0;i<2;i++)
        #pragma unroll
        for (int j=0;j<4;j++) {
            wmma::store_matrix_sync(stage, c[i][j], 20, wmma::mem_row_major);
            __syncwarp();
            int gmb = m0 + warp_m*32 + i*16;
            int gnb = n0 + warp_n*64 + j*16;
            #pragma unroll
            for (int e = lane; e < 256; e += 32) {
                int r = e >> 4, cc = e & 15;
                float val = stage[r*20+cc] + bias[gnb+cc];
                if (RND) val = wmma::__float_to_tf32(val);   // pre-round for flash
                C[(size_t)(gmb+r)*N + gnb+cc] = val;
            }
            __syncwarp();
        }
}

__global__ __launch_bounds__(256,2) void gemm_bias_kernel(
    const __nv_bfloat16* __restrict__ Ahi, const __nv_bfloat16* __restrict__ Alo,
    const __nv_bfloat16* __restrict__ Whi, const __nv_bfloat16* __restrict__ Wlo,
    const float* __restrict__ bias, float* __restrict__ C,
    int M, int N, int K)
{
    gemm_bias_body<false>(Ahi, Alo, Whi, Wlo, bias, C, M, N, K);
}

// Fused QKV: grid.z in {0,1,2} selects weight slice and output (tf32-rounded)
__global__ __launch_bounds__(256,2) void gemm_qkv_kernel(
    const __nv_bfloat16* __restrict__ xhi, const __nv_bfloat16* __restrict__ xlo,
    const __nv_bfloat16* __restrict__ whi, const __nv_bfloat16* __restrict__ wlo,
    const float* __restrict__ bq, const float* __restrict__ bk, const float* __restrict__ bv,
    float* __restrict__ Qo, float* __restrict__ Ko, float* __restrict__ Vo)
{
    const int z = blockIdx.z;
    const float* bias = (z == 0) ? bq : (z == 1) ? bk : bv;
    float* C = (z == 0) ? Qo : (z == 1) ? Ko : Vo;
    gemm_bias_body<true>(xhi, xlo, whi + (size_t)z*DD, wlo + (size_t)z*DD, bias, C, MTOT, D_, D_);
}

// ---------------------------------------------------------------------------
// Flash attention (causal), TF32, BR=64, 2 CTAs/SM.
// Register-resident O accumulators + hoisted Q fragments + cp.async KV
// double-buffering. Inputs pre-rounded to tf32 (no cvt in the hot loop).
// smem: Ssm [64][68] (Q staging -> S/P -> final O), KV 2 stages of
// (K[64][68] + V[64][68]), m/l/alpha rows.  Total 87,808 B -> 2 CTAs/SM.
// ---------------------------------------------------------------------------
#define BR 64
#define BC 64
#define QPITCH 68
#define SSZ   (64*QPITCH)          // 4352 floats
#define KVST  (2*SSZ)              // one stage: K+V

__global__ __launch_bounds__(256,2) void flash_kernel(
    const float* __restrict__ Q, const float* __restrict__ K,
    const float* __restrict__ V, float* __restrict__ Aout)
{
    extern __shared__ float sm[];
    float* Ssm  = sm;                      // [64][68]
    float* KVs  = sm + SSZ;                // 2 stages
    float* mrow = sm + SSZ + 2*KVST;       // [64]
    float* lrow = mrow + 64;               // [64]
    float* arow = lrow + 64;               // [64]
    const uint32_t smbase = (uint32_t)__cvta_generic_to_shared(sm);

    const int tid  = threadIdx.x;
    const int w    = tid >> 5;
    const int lane = tid & 31;
    const int wm   = w >> 1;               // 0..3 (rows)
    const int wn   = w & 1;                // 0..1 (cols)
    const int bh   = blockIdx.y;
    const int b    = bh / H_;
    const int h    = bh % H_;
    const int bx   = (int)gridDim.x - 1 - (int)blockIdx.x;  // heavy tiles first
    const int qt0  = bx * BR;
    const float scale = 0.125f;            // 1/sqrt(64), exact power of 2

    auto issue_kv = [&](int j, int s) {
        const size_t kvbase = (size_t)(b*T_ + j*BC) * D_ + h*HD_;
        #pragma unroll
        for (int idx = tid; idx < 2048; idx += 256) {
            int which = idx >> 10;
            int e = idx & 1023;
            int r = e >> 4, cg = e & 15;
            const float* src = which ? V : K;
            uint32_t daddr = smbase +
                (uint32_t)(SSZ + s*KVST + which*SSZ + r*QPITCH + cg*4)*4u;
            cp16(daddr, &src[kvbase + (size_t)r*D_ + cg*4]);
        }
        asm volatile("cp.async.commit_group;");
    };

    issue_kv(0, 0);   // overlap with Q staging

    // stage Q (scaled) into Ssm, build hoisted fragments
    const size_t qbase = (size_t)(b*T_ + qt0) * D_ + h*HD_;
    #pragma unroll
    for (int idx = tid; idx < 1024; idx += 256) {
        int r = idx >> 4, cg = idx & 15;
        float4 v = *reinterpret_cast<const float4*>(&Q[qbase + (size_t)r*D_ + cg*4]);
        v.x *= scale; v.y *= scale; v.z *= scale; v.w *= scale;
        *reinterpret_cast<float4*>(&Ssm[r*QPITCH + cg*4]) = v;
    }
    if (tid < 64) { mrow[tid] = -INFINITY; lrow[tid] = 0.f; }
    __syncthreads();

    wmma::fragment<wmma::matrix_a,16,16,8,wmma::precision::tf32,wmma::row_major> qf[8];
    #pragma unroll
    for (int kk8 = 0; kk8 < 8; kk8++)
        wmma::load_matrix_sync(qf[kk8], &Ssm[(wm*16)*QPITCH + kk8*8], QPITCH);

    // register-resident O: rows wm*16..+16, cols wn*32..+32
    wmma::fragment<wmma::accumulator,16,16,8,float> o[2];
    #pragma unroll
    for (int jj=0;jj<2;jj++) wmma::fill_fragment(o[jj], 0.f);
    __syncthreads();   // Ssm free for reuse as S

    const int njt = bx + 1;  // causal
    for (int j = 0; j < njt; j++) {
        const int cur = j & 1;
        if (j + 1 < njt) {
            issue_kv(j+1, cur^1);
            asm volatile("cp.async.wait_group 1;");
        } else {
            asm volatile("cp.async.wait_group 0;");
        }
        __syncthreads();

        const float* Ksm = KVs + cur*KVST;
        const float* Vsm = Ksm + SSZ;

        // S = Qs @ K^T : [64x64]; warps 4(m) x 2(n), each 16x32
        {
            wmma::fragment<wmma::accumulator,16,16,8,float> cfr[2];
            #pragma unroll
            for (int jj=0;jj<2;jj++) wmma::fill_fragment(cfr[jj], 0.f);
            #pragma unroll
            for (int kk8 = 0; kk8 < 8; kk8++) {
                wmma::fragment<wmma::matrix_b,16,16,8,wmma::precision::tf32,wmma::col_major> bf[2];
                #pragma unroll
                for (int jj=0;jj<2;jj++)
                    wmma::load_matrix_sync(bf[jj], &Ksm[(wn*32+jj*16)*QPITCH + kk8*8], QPITCH);
                #pragma unroll
                for (int jj=0;jj<2;jj++)
                    wmma::mma_sync(cfr[jj], qf[kk8], bf[jj], cfr[jj]);
            }
            #pragma unroll
            for (int jj=0;jj<2;jj++)
                wmma::store_matrix_sync(&Ssm[(wm*16)*QPITCH + wn*32+jj*16],
                                        cfr[jj], QPITCH, wmma::mem_row_major);
        }
        __syncthreads();

        // online softmax: 4 threads per row; P stored tf32-rounded
        {
            const int r = tid >> 2, quad = tid & 3;
            const int qrow = qt0 + r;
            const float mold = mrow[r];
            int clim = qrow - (j*BC);
            if (clim > BC-1) clim = BC-1;
            const int c0 = quad*16;
            float mt = -INFINITY;
            #pragma unroll
            for (int c = c0; c < c0+16; c++)
                if (c <= clim) mt = fmaxf(mt, Ssm[r*QPITCH+c]);
            mt = fmaxf(mt, __shfl_xor_sync(0xffffffffu, mt, 1));
            mt = fmaxf(mt, __shfl_xor_sync(0xffffffffu, mt, 2));
            const float mnew = fmaxf(mold, mt);
            const float alpha = __expf(mold - mnew);
            float lsum = 0.f;
            #pragma unroll
            for (int c = c0; c < c0+16; c++) {
                float p = (c <= clim) ? __expf(Ssm[r*QPITCH+c] - mnew) : 0.f;
                Ssm[r*QPITCH+c] = wmma::__float_to_tf32(p);
                lsum += p;
            }
            lsum += __shfl_xor_sync(0xffffffffu, lsum, 1);
            lsum += __shfl_xor_sync(0xffffffffu, lsum, 2);
            if (quad == 0) {
                mrow[r] = mnew;
                lrow[r] = lrow[r]*alpha + lsum;
                arow[r] = alpha;
            }
        }
        __syncthreads();

        // O = O*alpha (+= P@V).  De-facto m16n16 f32 acc layout:
        // elems {0,1,4,5} -> row lane>>2; {2,3,6,7} -> row+8.
        {
            const float a0 = arow[wm*16 + (lane>>2)];
            const float a1 = arow[wm*16 + (lane>>2) + 8];
            #pragma unroll
            for (int jj=0;jj<2;jj++) {
                o[jj].x[0]*=a0; o[jj].x[1]*=a0; o[jj].x[4]*=a0; o[jj].x[5]*=a0;
                o[jj].x[2]*=a1; o[jj].x[3]*=a1; o[jj].x[6]*=a1; o[jj].x[7]*=a1;
            }
            #pragma unroll
            for (int kk8 = 0; kk8 < 8; kk8++) {
                wmma::fragment<wmma::matrix_a,16,16,8,wmma::precision::tf32,wmma::row_major> af;
                wmma::load_matrix_sync(af, &Ssm[(wm*16)*QPITCH + kk8*8], QPITCH);
                wmma::fragment<wmma::matrix_b,16,16,8,wmma::precision::tf32,wmma::row_major> bf[2];
                #pragma unroll
                for (int jj=0;jj<2;jj++)
                    wmma::load_matrix_sync(bf[jj], &Vsm[(kk8*8)*QPITCH + wn*32 + jj*16], QPITCH);
                #pragma unroll
                for (int jj=0;jj<2;jj++)
                    wmma::mma_sync(o[jj], af, bf[jj], o[jj]);
            }
        }
        __syncthreads();   // protect Ssm (P) and KV stage before next-iter reuse
    }

    // epilogue: O -> Ssm, normalize by l, write out (canonical layout)
    #pragma unroll
    for (int jj=0;jj<2;jj++)
        wmma::store_matrix_sync(&Ssm[(wm*16)*QPITCH + wn*32 + jj*16], o[jj], QPITCH,
                                wmma::mem_row_major);
    __syncthreads();
    {
        const size_t obase = (size_t)(b*T_ + qt0) * D_ + h*HD_;
        for (int idx = tid; idx < 64*64; idx += 256) {
            int r = idx >> 6, c = idx & 63;
            Aout[obase + (size_t)r*D_ + c] = Ssm[r*QPITCH+c] / lrow[r];
        }
    }
}

// ---------------------------------------------------------------------------
// Launch
// ---------------------------------------------------------------------------
static const int FLASH_SMEM =
    (SSZ + 2*KVST + 3*64) * (int)sizeof(float);   // 87,808 B

extern "C" void kernel_launch(void* const* d_in, const int* in_sizes, int n_in,
                              void* d_out, int out_size)
{
    const float* x  = (const float*)d_in[0];
    const float* wq = (const float*)d_in[1];
    const float* bq = (const float*)d_in[2];
    const float* wk = (const float*)d_in[3];
    const float* bk = (const float*)d_in[4];
    const float* wv = (const float*)d_in[5];
    const float* bv = (const float*)d_in[6];
    const float* wo = (const float*)d_in[7];
    const float* bo = (const float*)d_in[8];
    // d_in[9] is the causal mask; causality is applied analytically in flash_kernel.
    float* out = (float*)d_out;

    float *qb, *kb, *vb, *ab;
    __nv_bfloat16 *xhi, *xlo, *ahi, *alo, *whi, *wlo;
    cudaGetSymbolAddress((void**)&qb, g_Q);
    cudaGetSymbolAddress((void**)&kb, g_K);
    cudaGetSymbolAddress((void**)&vb, g_V);
    cudaGetSymbolAddress((void**)&ab, g_A);
    cudaGetSymbolAddress((void**)&xhi, g_xhi);
    cudaGetSymbolAddress((void**)&xlo, g_xlo);
    cudaGetSymbolAddress((void**)&ahi, g_ahi);
    cudaGetSymbolAddress((void**)&alo, g_alo);
    cudaGetSymbolAddress((void**)&whi, g_whi);
    cudaGetSymbolAddress((void**)&wlo, g_wlo);

    cudaFuncSetAttribute(flash_kernel, cudaFuncAttributeMaxDynamicSharedMemorySize, FLASH_SMEM);
    cudaFuncSetAttribute(gemm_qkv_kernel, cudaFuncAttributeMaxDynamicSharedMemorySize, GEMM_DSMEM);
    cudaFuncSetAttribute(gemm_bias_kernel, cudaFuncAttributeMaxDynamicSharedMemorySize, GEMM_DSMEM);

    // split inputs into bf16 hi/lo
    split_kernel<<<512, 256>>>(x, xhi, xlo, MTOT*D_);
    dim3 wsplit_grid(128, 1, 4);
    split_w_kernel<<<wsplit_grid, 256>>>(wq, wk, wv, wo, whi, wlo);

    dim3 qkv_grid(MTOT/BM, D_/BN, 3);   // (64, 8, 3)
    gemm_qkv_kernel<<<qkv_grid, 256, GEMM_DSMEM>>>(xhi, xlo, whi, wlo, bq, bk, bv, qb, kb, vb);

    dim3 flash_grid(T_/BR, B_*H_);      // (32, 64)
    flash_kernel<<<flash_grid, 256, FLASH_SMEM>>>(qb, kb, vb, ab);

    split_kernel<<<512, 256>>>(ab, ahi, alo, MTOT*D_);

    dim3 gemm_grid(MTOT/BM, D_/BN);     // (64, 8)
    gemm_bias_kernel<<<gemm_grid, 256, GEMM_DSMEM>>>(ahi, alo, whi + 3*(size_t)DD, wlo + 3*(size_t)DD,
                                                     bo, out, MTOT, D_, D_);
}

// round 17
// speedup vs baseline: 5.1053x; 1.4313x over previous
#include <cuda_runtime.h>
#include <cstdint>
#include <cuda_bf16.h>
#include <mma.h>
#include <math.h>

using namespace nvcuda;

#define B_  4
#define T_  2048
#define D_  1024
#define H_  16
#define HD_ 64
#define MTOT (B_*T_)   // 8192
#define DD  (D_*D_)    // 1048576

// Scratch (device globals: allocation-free rule)
__device__ float g_Q[MTOT*D_];
__device__ float g_K[MTOT*D_];
__device__ float g_V[MTOT*D_];
__device__ float g_A[MTOT*D_];
// bf16 hi/lo split operands
__device__ __nv_bfloat16 g_xhi[MTOT*D_];
__device__ __nv_bfloat16 g_xlo[MTOT*D_];
__device__ __nv_bfloat16 g_ahi[MTOT*D_];
__device__ __nv_bfloat16 g_alo[MTOT*D_];
__device__ __nv_bfloat16 g_whi[4*DD];   // wq, wk, wv, wo
__device__ __nv_bfloat16 g_wlo[4*DD];

// ---------------------------------------------------------------------------
// Split fp32 -> bf16 hi + bf16 lo
// ---------------------------------------------------------------------------
__device__ __forceinline__ void split_body(
    const float* __restrict__ src, __nv_bfloat16* __restrict__ hi,
    __nv_bfloat16* __restrict__ lo, int n)
{
    int i = blockIdx.x*blockDim.x + threadIdx.x;
    int stride = gridDim.x*blockDim.x;
    for (; i < n/4; i += stride) {
        float4 v = reinterpret_cast<const float4*>(src)[i];
        __nv_bfloat16 h0 = __float2bfloat16(v.x);
        __nv_bfloat16 h1 = __float2bfloat16(v.y);
        __nv_bfloat16 h2 = __float2bfloat16(v.z);
        __nv_bfloat16 h3 = __float2bfloat16(v.w);
        __nv_bfloat162 hA; hA.x = h0; hA.y = h1;
        __nv_bfloat162 hB; hB.x = h2; hB.y = h3;
        __nv_bfloat162 lA, lB;
        lA.x = __float2bfloat16(v.x - __bfloat162float(h0));
        lA.y = __float2bfloat16(v.y - __bfloat162float(h1));
        lB.x = __float2bfloat16(v.z - __bfloat162float(h2));
        lB.y = __float2bfloat16(v.w - __bfloat162float(h3));
        reinterpret_cast<__nv_bfloat162*>(hi)[i*2+0] = hA;
        reinterpret_cast<__nv_bfloat162*>(hi)[i*2+1] = hB;
        reinterpret_cast<__nv_bfloat162*>(lo)[i*2+0] = lA;
        reinterpret_cast<__nv_bfloat162*>(lo)[i*2+1] = lB;
    }
}

__global__ __launch_bounds__(256) void split_kernel(
    const float* __restrict__ src, __nv_bfloat16* __restrict__ hi,
    __nv_bfloat16* __restrict__ lo, int n)
{
    split_body(src, hi, lo, n);
}

// All 4 weight splits in one launch: grid.z selects the weight
__global__ __launch_bounds__(256) void split_w_kernel(
    const float* __restrict__ wq, const float* __restrict__ wk,
    const float* __restrict__ wv, const float* __restrict__ wo,
    __nv_bfloat16* __restrict__ whi, __nv_bfloat16* __restrict__ wlo)
{
    const int z = blockIdx.z;
    const float* src = (z==0) ? wq : (z==1) ? wk : (z==2) ? wv : wo;
    split_body(src, whi + (size_t)z*DD, wlo + (size_t)z*DD, DD);
}

__device__ __forceinline__ void cp16(uint32_t saddr, const void* g) {
    asm volatile("cp.async.cg.shared.global [%0], [%1], 16;" :: "r"(saddr), "l"(g));
}

// ---------------------------------------------------------------------------
// GEMM: C[M,N] = A[M,K] @ W[N,K]^T + bias, bf16x3, 2-stage cp.async pipeline
// RND: round output to tf32 (for Q/K/V feeding the tf32 flash kernel).
// ---------------------------------------------------------------------------
#define BM 128
#define BN 128
#define BKK 32
#define TPB 40                       // bf16 tile row pitch (80 bytes)
#define TSTB (128*TPB)               // bf16 elems per tile
static const int GEMM_DSMEM = (8*TSTB) * (int)sizeof(__nv_bfloat16);   // 81920 B

template <bool RND>
__device__ __forceinline__ void gemm_bias_body(
    const __nv_bfloat16* __restrict__ Ahi, const __nv_bfloat16* __restrict__ Alo,
    const __nv_bfloat16* __restrict__ Whi, const __nv_bfloat16* __restrict__ Wlo,
    const float* __restrict__ bias, float* __restrict__ C,
    int M, int N, int K)
{
    extern __shared__ __nv_bfloat16 dynsmb[];
    const uint32_t smbase = (uint32_t)__cvta_generic_to_shared(dynsmb);

    const int tid  = threadIdx.x;
    const int w    = tid >> 5;
    const int lane = tid & 31;
    const int warp_m = w >> 1;           // 0..3
    const int warp_n = w & 1;            // 0..1
    const int m0 = blockIdx.x * BM;
    const int n0 = blockIdx.y * BN;

    wmma::fragment<wmma::accumulator,16,16,16,float> c[2][4];
    #pragma unroll
    for (int i=0;i<2;i++)
        #pragma unroll
        for (int j=0;j<4;j++) wmma::fill_fragment(c[i][j], 0.f);

    const int NIT = K / BKK;   // 32

    auto issue_tiles = [&](int k0, int s) {
        const __nv_bfloat16* srcs[4] = { Ahi, Alo, Whi, Wlo };
        #pragma unroll
        for (int t = 0; t < 4; t++) {
            const uint32_t tb = smbase + (uint32_t)((s*4 + t)*TSTB)*2u;
            const __nv_bfloat16* src = srcs[t];
            const int r0 = (t < 2) ? m0 : n0;
            #pragma unroll
            for (int idx = tid; idx < 512; idx += 256) {
                int r = idx >> 2, cg = idx & 3;   // 16B chunk = 8 bf16
                cp16(tb + (uint32_t)(r*TPB + cg*8)*2u,
                     &src[(size_t)(r0+r)*K + k0 + cg*8]);
            }
        }
        asm volatile("cp.async.commit_group;");
    };

    issue_tiles(0, 0);

    for (int it = 0; it < NIT; it++) {
        const int cur = it & 1;
        if (it + 1 < NIT) {
            issue_tiles((it+1)*BKK, (it+1) & 1);
            asm volatile("cp.async.wait_group 1;");
        } else {
            asm volatile("cp.async.wait_group 0;");
        }
        __syncthreads();

        const __nv_bfloat16* At_hi = dynsmb + (cur*4 + 0)*TSTB;
        const __nv_bfloat16* At_lo = dynsmb + (cur*4 + 1)*TSTB;
        const __nv_bfloat16* Wt_hi = dynsmb + (cur*4 + 2)*TSTB;
        const __nv_bfloat16* Wt_lo = dynsmb + (cur*4 + 3)*TSTB;

        #pragma unroll
        for (int kk = 0; kk < BKK; kk += 16) {
            wmma::fragment<wmma::matrix_a,16,16,16,__nv_bfloat16,wmma::row_major> ahi[2], alo[2];
            wmma::fragment<wmma::matrix_b,16,16,16,__nv_bfloat16,wmma::col_major> bhi[4], blo[4];
            #pragma unroll
            for (int i=0;i<2;i++) {
                wmma::load_matrix_sync(ahi[i], &At_hi[(warp_m*32 + i*16)*TPB + kk], TPB);
                wmma::load_matrix_sync(alo[i], &At_lo[(warp_m*32 + i*16)*TPB + kk], TPB);
            }
            #pragma unroll
            for (int j=0;j<4;j++) {
                wmma::load_matrix_sync(bhi[j], &Wt_hi[(warp_n*64 + j*16)*TPB + kk], TPB);
                wmma::load_matrix_sync(blo[j], &Wt_lo[(warp_n*64 + j*16)*TPB + kk], TPB);
            }
            #pragma unroll
            for (int i=0;i<2;i++)
                #pragma unroll
                for (int j=0;j<4;j++) {
                    wmma::mma_sync(c[i][j], ahi[i], blo[j], c[i][j]);
                    wmma::mma_sync(c[i][j], alo[i], bhi[j], c[i][j]);
                    wmma::mma_sync(c[i][j], ahi[i], bhi[j], c[i][j]);
                }
        }
        __syncthreads();
    }

    // epilogue with bias; reuse pipeline smem as per-warp float staging [16][20]
    float* stage = reinterpret_cast<float*>(dynsmb) + w*(16*20);
    #pragma unroll
    for (int i=0;i<2;i++)
        #pragma unroll
        for (int j=0;j<4;j++) {
            wmma::store_matrix_sync(stage, c[i][j], 20, wmma::mem_row_major);
            __syncwarp();
            int gmb = m0 + warp_m*32 + i*16;
            int gnb = n0 + warp_n*64 + j*16;
            #pragma unroll
            for (int e = lane; e < 256; e += 32) {
                int r = e >> 4, cc = e & 15;
                float val = stage[r*20+cc] + bias[gnb+cc];
                if (RND) val = wmma::__float_to_tf32(val);   // pre-round for flash
                C[(size_t)(gmb+r)*N + gnb+cc] = val;
            }
            __syncwarp();
        }
}

__global__ __launch_bounds__(256,2) void gemm_bias_kernel(
    const __nv_bfloat16* __restrict__ Ahi, const __nv_bfloat16* __restrict__ Alo,
    const __nv_bfloat16* __restrict__ Whi, const __nv_bfloat16* __restrict__ Wlo,
    const float* __restrict__ bias, float* __restrict__ C,
    int M, int N, int K)
{
    gemm_bias_body<false>(Ahi, Alo, Whi, Wlo, bias, C, M, N, K);
}

// Fused QKV: grid.z in {0,1,2} selects weight slice and output (tf32-rounded)
__global__ __launch_bounds__(256,2) void gemm_qkv_kernel(
    const __nv_bfloat16* __restrict__ xhi, const __nv_bfloat16* __restrict__ xlo,
    const __nv_bfloat16* __restrict__ whi, const __nv_bfloat16* __restrict__ wlo,
    const float* __restrict__ bq, const float* __restrict__ bk, const float* __restrict__ bv,
    float* __restrict__ Qo, float* __restrict__ Ko, float* __restrict__ Vo)
{
    const int z = blockIdx.z;
    const float* bias = (z == 0) ? bq : (z == 1) ? bk : bv;
    float* C = (z == 0) ? Qo : (z == 1) ? Ko : Vo;
    gemm_bias_body<true>(xhi, xlo, whi + (size_t)z*DD, wlo + (size_t)z*DD, bias, C, MTOT, D_, D_);
}

// ---------------------------------------------------------------------------
// Flash attention (causal), raw mma.m16n8k8 tf32, in-register softmax.
// BR=64, 8 warps: wm=warp>>1 picks 16 rows, wn=warp&1 picks a 32-wide
// k-slice for S / PV. P never touches smem: acc regs {c0,c2,c1,c3} feed the
// PV mma directly, with V rows stored permuted [0,2,4,6,1,3,5,7] per 8-block.
// Each warp accumulates a full-width (64-col) partial O over its k-slice;
// the two slices are summed once in smem at the epilogue.
// ---------------------------------------------------------------------------
#define BR 64
#define BC 64
#define QPITCH 68
#define SSZ   (64*QPITCH)          // 4352 floats
#define KVST  (2*SSZ)              // one stage: K + V

#define MMA_TF32(d, a0,a1,a2,a3, b0,b1) \
    asm volatile("mma.sync.aligned.m16n8k8.row.col.f32.tf32.tf32.f32 " \
        "{%0,%1,%2,%3}, {%4,%5,%6,%7}, {%8,%9}, {%0,%1,%2,%3};" \
        : "+f"(d[0]), "+f"(d[1]), "+f"(d[2]), "+f"(d[3]) \
        : "r"(a0), "r"(a1), "r"(a2), "r"(a3), "r"(b0), "r"(b1))

__global__ __launch_bounds__(256,2) void flash_kernel(
    const float* __restrict__ Q, const float* __restrict__ K,
    const float* __restrict__ V, float* __restrict__ Aout)
{
    extern __shared__ float sm[];
    float* Qsm  = sm;                       // [64][68] Q staging
    float* KVs  = sm + SSZ;                 // 2 stages x (K[64][68] + V[64][68])
    float* part = sm + SSZ + 2*KVST;        // [2 parity][2 wn][64] float2
    float* lsm  = part + 512;               // [64] 1/l
    const uint32_t smbase = (uint32_t)__cvta_generic_to_shared(sm);

    const int tid  = threadIdx.x;
    const int w    = tid >> 5;
    const int lane = tid & 31;
    const int wm   = w >> 1;                // 0..3
    const int wn   = w & 1;                 // 0..1
    const int gr   = lane >> 2;             // 0..7
    const int gc   = lane & 3;              // 0..3
    const int bh   = blockIdx.y;
    const int b    = bh / H_;
    const int h    = bh % H_;
    const int bx   = (int)gridDim.x - 1 - (int)blockIdx.x;  // heavy tiles first
    const int qt0  = bx * BR;
    const int row0 = wm*16 + gr;            // tile-local row of acc elems 0,1
    const float scale = 0.125f;             // 1/sqrt(64), exact in tf32

    auto issue_kv = [&](int j, int s) {
        const size_t kvbase = (size_t)(b*T_ + j*BC) * D_ + h*HD_;
        #pragma unroll
        for (int idx = tid; idx < 2048; idx += 256) {
            int which = idx >> 10;
            int e = idx & 1023;
            int r = e >> 4, cg = e & 15;
            // V rows permuted within 8-blocks: [0,2,4,6,1,3,5,7]
            int dr = which ? ((r & ~7) | ((r & 1) << 2) | ((r & 7) >> 1)) : r;
            const float* src = which ? V : K;
            uint32_t daddr = smbase +
                (uint32_t)(SSZ + s*KVST + which*SSZ + dr*QPITCH + cg*4)*4u;
            cp16(daddr, &src[kvbase + (size_t)r*D_ + cg*4]);
        }
        asm volatile("cp.async.commit_group;");
    };

    issue_kv(0, 0);

    // stage Q (scaled)
    const size_t qbase = (size_t)(b*T_ + qt0) * D_ + h*HD_;
    #pragma unroll
    for (int idx = tid; idx < 1024; idx += 256) {
        int r = idx >> 4, cg = idx & 15;
        float4 v = *reinterpret_cast<const float4*>(&Q[qbase + (size_t)r*D_ + cg*4]);
        v.x *= scale; v.y *= scale; v.z *= scale; v.w *= scale;
        *reinterpret_cast<float4*>(&Qsm[r*QPITCH + cg*4]) = v;
    }
    __syncthreads();

    // hoisted Q A-fragments (m16k8 tf32): a0(gr,gc) a1(gr+8,gc) a2(gr,gc+4) a3(gr+8,gc+4)
    uint32_t qa[8][4];
    #pragma unroll
    for (int k8 = 0; k8 < 8; k8++) {
        qa[k8][0] = __float_as_uint(Qsm[(row0  )*QPITCH + k8*8 + gc    ]);
        qa[k8][1] = __float_as_uint(Qsm[(row0+8)*QPITCH + k8*8 + gc    ]);
        qa[k8][2] = __float_as_uint(Qsm[(row0  )*QPITCH + k8*8 + gc + 4]);
        qa[k8][3] = __float_as_uint(Qsm[(row0+8)*QPITCH + k8*8 + gc + 4]);
    }

    // full-width partial O (this warp's k-slice): 8 n-frags of m16n8
    float o[8][4];
    #pragma unroll
    for (int nn = 0; nn < 8; nn++) { o[nn][0]=0.f; o[nn][1]=0.f; o[nn][2]=0.f; o[nn][3]=0.f; }
    float m_run0 = -INFINITY, m_run1 = -INFINITY;
    float l_run0 = 0.f, l_run1 = 0.f;

    float2* part2 = reinterpret_cast<float2*>(part);

    const int njt = bx + 1;  // causal
    for (int j = 0; j < njt; j++) {
        const int cur = j & 1;
        asm volatile("cp.async.wait_group 0;");
        __syncthreads();                       // KV stage cur ready & visible
        if (j + 1 < njt) issue_kv(j+1, cur^1); // overwrite safe: all past j-1 PV

        const float* Ksm = KVs + cur*KVST;
        const float* Vsm = Ksm + SSZ;

        // ---- S = Qs @ K^T : this warp rows [wm*16,+16), cols [wn*32,+32)
        float sa[4][4];
        #pragma unroll
        for (int jj = 0; jj < 4; jj++) { sa[jj][0]=0.f; sa[jj][1]=0.f; sa[jj][2]=0.f; sa[jj][3]=0.f; }
        #pragma unroll
        for (int k8 = 0; k8 < 8; k8++) {
            #pragma unroll
            for (int jj = 0; jj < 4; jj++) {
                const int n = wn*32 + jj*8 + gr;
                uint32_t b0 = __float_as_uint(Ksm[n*QPITCH + k8*8 + gc    ]);
                uint32_t b1 = __float_as_uint(Ksm[n*QPITCH + k8*8 + gc + 4]);
                MMA_TF32(sa[jj], qa[k8][0], qa[k8][1], qa[k8][2], qa[k8][3], b0, b1);
            }
        }

        // ---- causal mask (diagonal tile only): local col > local row -> -inf
        if (j == bx) {
            #pragma unroll
            for (int jj = 0; jj < 4; jj++) {
                const int c0 = wn*32 + jj*8 + 2*gc;
                if (c0     > row0    ) sa[jj][0] = -INFINITY;
                if (c0 + 1 > row0    ) sa[jj][1] = -INFINITY;
                if (c0     > row0 + 8) sa[jj][2] = -INFINITY;
                if (c0 + 1 > row0 + 8) sa[jj][3] = -INFINITY;
            }
        }

        // ---- in-register softmax (this warp's 32 cols)
        float mx0 = -INFINITY, mx1 = -INFINITY;
        #pragma unroll
        for (int jj = 0; jj < 4; jj++) {
            mx0 = fmaxf(mx0, fmaxf(sa[jj][0], sa[jj][1]));
            mx1 = fmaxf(mx1, fmaxf(sa[jj][2], sa[jj][3]));
        }
        mx0 = fmaxf(mx0, __shfl_xor_sync(0xffffffffu, mx0, 1));
        mx0 = fmaxf(mx0, __shfl_xor_sync(0xffffffffu, mx0, 2));
        mx1 = fmaxf(mx1, __shfl_xor_sync(0xffffffffu, mx1, 1));
        mx1 = fmaxf(mx1, __shfl_xor_sync(0xffffffffu, mx1, 2));
        // guard: fully-masked half -> use 0 so exp(-inf-0)=0, not NaN
        const float mu0 = (mx0 == -INFINITY) ? 0.f : mx0;
        const float mu1 = (mx1 == -INFINITY) ? 0.f : mx1;
        float s0 = 0.f, s1 = 0.f;
        #pragma unroll
        for (int jj = 0; jj < 4; jj++) {
            sa[jj][0] = __expf(sa[jj][0] - mu0);
            sa[jj][1] = __expf(sa[jj][1] - mu0);
            sa[jj][2] = __expf(sa[jj][2] - mu1);
            sa[jj][3] = __expf(sa[jj][3] - mu1);
            s0 += sa[jj][0] + sa[jj][1];
            s1 += sa[jj][2] + sa[jj][3];
        }
        s0 += __shfl_xor_sync(0xffffffffu, s0, 1);
        s0 += __shfl_xor_sync(0xffffffffu, s0, 2);
        s1 += __shfl_xor_sync(0xffffffffu, s1, 1);
        s1 += __shfl_xor_sync(0xffffffffu, s1, 2);

        if (gc == 0) {
            part2[(cur*2 + wn)*64 + row0    ] = make_float2(mx0, s0);
            part2[(cur*2 + wn)*64 + row0 + 8] = make_float2(mx1, s1);
        }
        __syncthreads();

        // ---- merge the two warp-halves + running state (all in regs)
        float2 a0 = part2[(cur*2 + 0)*64 + row0    ];
        float2 b0v= part2[(cur*2 + 1)*64 + row0    ];
        float2 a1 = part2[(cur*2 + 0)*64 + row0 + 8];
        float2 b1v= part2[(cur*2 + 1)*64 + row0 + 8];
        const float mn0 = fmaxf(m_run0, fmaxf(a0.x, b0v.x));
        const float mn1 = fmaxf(m_run1, fmaxf(a1.x, b1v.x));
        const float alpha0 = __expf(m_run0 - mn0);   // -inf -> 0 (mn finite)
        const float alpha1 = __expf(m_run1 - mn1);
        const float lt0 = a0.y*__expf(a0.x - mn0) + b0v.y*__expf(b0v.x - mn0);
        const float lt1 = a1.y*__expf(a1.x - mn1) + b1v.y*__expf(b1v.x - mn1);
        l_run0 = l_run0*alpha0 + lt0;  m_run0 = mn0;
        l_run1 = l_run1*alpha1 + lt1;  m_run1 = mn1;
        const float f0 = __expf(mx0 - mn0);          // own-half rescale
        const float f1 = __expf(mx1 - mn1);

        // ---- rescale P (tf32-rounded) and O
        uint32_t pa[4][4];
        #pragma unroll
        for (int jj = 0; jj < 4; jj++) {
            pa[jj][0] = __float_as_uint(wmma::__float_to_tf32(sa[jj][0]*f0));
            pa[jj][1] = __float_as_uint(wmma::__float_to_tf32(sa[jj][1]*f0));
            pa[jj][2] = __float_as_uint(wmma::__float_to_tf32(sa[jj][2]*f1));
            pa[jj][3] = __float_as_uint(wmma::__float_to_tf32(sa[jj][3]*f1));
        }
        #pragma unroll
        for (int nn = 0; nn < 8; nn++) {
            o[nn][0] *= alpha0; o[nn][1] *= alpha0;
            o[nn][2] *= alpha1; o[nn][3] *= alpha1;
        }

        // ---- O += P @ V over this warp's k-slice (4 chunks of 8)
        // P acc regs feed A directly: a0=c0, a1=c2, a2=c1, a3=c3 with V rows
        // stored slot-permuted so slot q<->col 2q, q+4<->2q+1.
        #pragma unroll
        for (int jj = 0; jj < 4; jj++) {
            const int kb = (wn*4 + jj)*8;
            #pragma unroll
            for (int nn = 0; nn < 8; nn++) {
                uint32_t b0 = __float_as_uint(Vsm[(kb + gc    )*QPITCH + nn*8 + gr]);
                uint32_t b1 = __float_as_uint(Vsm[(kb + gc + 4)*QPITCH + nn*8 + gr]);
                MMA_TF32(o[nn], pa[jj][0], pa[jj][2], pa[jj][1], pa[jj][3], b0, b1);
            }
        }
    }

    // ---- epilogue: combine the two k-slice partials via smem, normalize
    __syncthreads();                           // all PV reads done; KV reusable
    float* Os = KVs + wn*SSZ;                  // per-wn [64][68] buffer
    #pragma unroll
    for (int nn = 0; nn < 8; nn++) {
        *reinterpret_cast<float2*>(&Os[(row0  )*QPITCH + nn*8 + 2*gc]) = make_float2(o[nn][0], o[nn][1]);
        *reinterpret_cast<float2*>(&Os[(row0+8)*QPITCH + nn*8 + 2*gc]) = make_float2(o[nn][2], o[nn][3]);
    }
    if (wn == 0 && gc == 0) {
        lsm[row0    ] = __frcp_rn(l_run0);
        lsm[row0 + 8] = __frcp_rn(l_run1);
    }
    __syncthreads();
    {
        const size_t obase = (size_t)(b*T_ + qt0) * D_ + h*HD_;
        for (int idx = tid; idx < 4096; idx += 256) {
            int r = idx >> 6, c = idx & 63;
            Aout[obase + (size_t)r*D_ + c] =
                (KVs[r*QPITCH + c] + KVs[SSZ + r*QPITCH + c]) * lsm[r];
        }
    }
}

// ---------------------------------------------------------------------------
// Launch
// ---------------------------------------------------------------------------
static const int FLASH_SMEM =
    (SSZ + 2*KVST + 512 + 64) * (int)sizeof(float);   // 89,344 B

extern "C" void kernel_launch(void* const* d_in, const int* in_sizes, int n_in,
                              void* d_out, int out_size)
{
    const float* x  = (const float*)d_in[0];
    const float* wq = (const float*)d_in[1];
    const float* bq = (const float*)d_in[2];
    const float* wk = (const float*)d_in[3];
    const float* bk = (const float*)d_in[4];
    const float* wv = (const float*)d_in[5];
    const float* bv = (const float*)d_in[6];
    const float* wo = (const float*)d_in[7];
    const float* bo = (const float*)d_in[8];
    // d_in[9] is the causal mask; causality is applied analytically in flash_kernel.
    float* out = (float*)d_out;

    float *qb, *kb, *vb, *ab;
    __nv_bfloat16 *xhi, *xlo, *ahi, *alo, *whi, *wlo;
    cudaGetSymbolAddress((void**)&qb, g_Q);
    cudaGetSymbolAddress((void**)&kb, g_K);
    cudaGetSymbolAddress((void**)&vb, g_V);
    cudaGetSymbolAddress((void**)&ab, g_A);
    cudaGetSymbolAddress((void**)&xhi, g_xhi);
    cudaGetSymbolAddress((void**)&xlo, g_xlo);
    cudaGetSymbolAddress((void**)&ahi, g_ahi);
    cudaGetSymbolAddress((void**)&alo, g_alo);
    cudaGetSymbolAddress((void**)&whi, g_whi);
    cudaGetSymbolAddress((void**)&wlo, g_wlo);

    cudaFuncSetAttribute(flash_kernel, cudaFuncAttributeMaxDynamicSharedMemorySize, FLASH_SMEM);
    cudaFuncSetAttribute(gemm_qkv_kernel, cudaFuncAttributeMaxDynamicSharedMemorySize, GEMM_DSMEM);
    cudaFuncSetAttribute(gemm_bias_kernel, cudaFuncAttributeMaxDynamicSharedMemorySize, GEMM_DSMEM);

    // split inputs into bf16 hi/lo
    split_kernel<<<512, 256>>>(x, xhi, xlo, MTOT*D_);
    dim3 wsplit_grid(128, 1, 4);
    split_w_kernel<<<wsplit_grid, 256>>>(wq, wk, wv, wo, whi, wlo);

    dim3 qkv_grid(MTOT/BM, D_/BN, 3);   // (64, 8, 3)
    gemm_qkv_kernel<<<qkv_grid, 256, GEMM_DSMEM>>>(xhi, xlo, whi, wlo, bq, bk, bv, qb, kb, vb);

    dim3 flash_grid(T_/BR, B_*H_);      // (32, 64)
    flash_kernel<<<flash_grid, 256, FLASH_SMEM>>>(qb, kb, vb, ab);

    split_kernel<<<512, 256>>>(ab, ahi, alo, MTOT*D_);

    dim3 gemm_grid(MTOT/BM, D_/BN);     // (64, 8)
    gemm_bias_kernel<<<gemm_grid, 256, GEMM_DSMEM>>>(ahi, alo, whi + 3*(size_t)DD, wlo + 3*(size_t)DD,
                                                     bo, out, MTOT, D_, D_);
}